// round 5
// baseline (speedup 1.0000x reference)
#include <cuda_runtime.h>
#include <math.h>

#define VOCAB 100000
#define EMB   100
#define HID   100
#define CTX   60
#define FACT  20
#define T     60

typedef unsigned long long u64;

// ---------------- scratch ----------------
__device__ float g_facts[CTX * EMB];
__device__ float g_h0[HID];
__device__ float g_gi[T * 3 * HID];
__device__ float g_H[T * HID];            // compact (k_final)
__device__ float g_Hp[T * 104];           // padded: [t][half*52 + j], pads stay 0
__device__ float g_sumexp[T];

__device__ __forceinline__ float sigmoidf_(float x) {
    return 1.0f / (1.0f + __expf(-x));
}
__device__ __forceinline__ void ffma2(u64 &d, u64 a, u64 b) {
    asm("fma.rn.f32x2 %0, %1, %2, %0;" : "+l"(d) : "l"(a), "l"(b));
}
__device__ __forceinline__ float f2_lo(u64 v) { return __int_as_float((int)(v & 0xffffffffull)); }
__device__ __forceinline__ float f2_hi(u64 v) { return __int_as_float((int)(v >> 32)); }
__device__ __forceinline__ u64 f2_pack(float x, float y) {
    return (u64)__float_as_uint(x) | ((u64)__float_as_uint(y) << 32);
}

// ---------------- K_pre: gi (blocks 0..59) + facts (blocks 60..119) ----------------
__global__ void __launch_bounds__(320) k_pre(const int* __restrict__ ctx,
                                             const float* __restrict__ emb_ctx,
                                             const int* __restrict__ desc,
                                             const float* __restrict__ emb_dec,
                                             const float* __restrict__ w_ih,
                                             const float* __restrict__ b_ih) {
    int bid = blockIdx.x;
    int j = threadIdx.x;
    if (bid < 60) {
        int t = bid;
        __shared__ __align__(16) float x[EMB];
        __shared__ int tok;
        if (j == 0) tok = (t == 0) ? 1 : desc[t - 1];
        __syncthreads();
        if (j < EMB) x[j] = emb_dec[(long)tok * EMB + j];
        __syncthreads();
        if (j < 3 * HID) {
            const float4* w4 = (const float4*)(w_ih + (long)j * EMB);
            const float4* x4 = (const float4*)x;
            float a0 = b_ih[j], a1 = 0.0f, a2 = 0.0f, a3 = 0.0f;
#pragma unroll
            for (int k = 0; k < 25; k++) {
                float4 w = w4[k];
                float4 h = x4[k];
                a0 += w.x * h.x; a1 += w.y * h.y; a2 += w.z * h.z; a3 += w.w * h.w;
            }
            g_gi[t * (3 * HID) + j] = (a0 + a1) + (a2 + a3);
        }
    } else {
        int f = bid - 60;
        if (f == 0 && j < T) g_sumexp[j] = 0.0f;
        __shared__ int toks[FACT];
        if (j < FACT) toks[j] = ctx[f * FACT + j];
        __syncthreads();
        if (j < EMB) {
            float ee = (float)j * (1.0f / 99.0f);
            float acc = 0.0f;
#pragma unroll
            for (int p = 0; p < FACT; p++) {
                float s = (float)p * (1.0f / 19.0f);
                float l = 1.0f - s - ee * (1.0f - 2.0f * s);
                acc += emb_ctx[(long)toks[p] * EMB + j] * l;
            }
            g_facts[f * EMB + j] = acc;
        }
    }
}

// ---------------- K2: h0 ----------------
__global__ void k_h0(const float* __restrict__ w1, const float* __restrict__ b1) {
    int j = blockIdx.x;
    int tid = threadIdx.x;
    const float* wr = w1 + (long)j * (CTX * HID);
    float acc = 0.0f;
    for (int k = tid; k < CTX * HID; k += 256)
        acc += g_facts[k] * wr[k];
    for (int off = 16; off; off >>= 1)
        acc += __shfl_down_sync(0xffffffffu, acc, off);
    __shared__ float s[8];
    if ((tid & 31) == 0) s[tid >> 5] = acc;
    __syncthreads();
    if (tid == 0) {
        float tot = 0.0f;
#pragma unroll
        for (int w = 0; w < 8; w++) tot += s[w];
        g_h0[j] = tot + b1[j];
    }
}

// ---------------- K3: GRU recurrence (600 thr, gi in smem, 2 bars/step) ----------------
__global__ void __launch_bounds__(600, 1) k_rnn(const float* __restrict__ w_hh,
                                                const float* __restrict__ b_hh) {
    extern __shared__ __align__(16) float dyn[];
    float* sgi = dyn;            // 18000
    float* h   = dyn + 18000;    // 100
    float* ps  = h + 100;        // 600

    int tid = threadIdx.x;
    int out = tid % 300;
    int half = tid / 300;

    u64 w2[25];
    {
        const u64* wr = (const u64*)(w_hh + (long)out * HID + half * 50);
#pragma unroll
        for (int k = 0; k < 25; k++) w2[k] = wr[k];
    }
    float bhr = 0.0f, bhz = 0.0f, bhn = 0.0f;
    if (tid < HID) {
        bhr = b_hh[tid];
        bhz = b_hh[HID + tid];
        bhn = b_hh[2 * HID + tid];
    }

    for (int i = tid; i < T * 3 * HID; i += 600) sgi[i] = g_gi[i];
    if (tid < HID) h[tid] = g_h0[tid];
    __syncthreads();

    for (int t = 0; t < T; t++) {
        {
            const u64* h2 = (const u64*)(h + half * 50);
            u64 a0 = 0ull, a1 = 0ull;
#pragma unroll
            for (int k = 0; k < 12; k++) {
                ffma2(a0, w2[2 * k], h2[2 * k]);
                ffma2(a1, w2[2 * k + 1], h2[2 * k + 1]);
            }
            ffma2(a0, w2[24], h2[24]);
            ps[tid] = (f2_lo(a0) + f2_hi(a0)) + (f2_lo(a1) + f2_hi(a1));
        }
        __syncthreads();

        if (tid < HID) {
            float ghr = ps[tid]       + ps[tid + 300] + bhr;
            float ghz = ps[tid + 100] + ps[tid + 400] + bhz;
            float ghn = ps[tid + 200] + ps[tid + 500] + bhn;
            const float* gi = sgi + t * 300;
            float r = sigmoidf_(gi[tid] + ghr);
            float z = sigmoidf_(gi[HID + tid] + ghz);
            float a = gi[2 * HID + tid] + r * ghn;
            float ex = __expf(2.0f * a);
            float n = 1.0f - __fdividef(2.0f, ex + 1.0f);
            float hn = (1.0f - z) * n + z * h[tid];
            h[tid] = hn;
            g_H[t * HID + tid] = hn;
            int idx = t * 104 + ((tid < 50) ? tid : (tid + 2));
            g_Hp[idx] = hn;
        }
        __syncthreads();
    }
}

// ---------------- K4: logits + per-step sum(exp), 2 vocab rows/thread ----------------
// Warp covers 32 rows: lane&15 -> rows (base+la, base+la+16); half=lane>>4 is k-chunk.
#define LB 256
__global__ void __launch_bounds__(LB, 2) k_logits(const float* __restrict__ w_out,
                                                  const float* __restrict__ b_out) {
    __shared__ __align__(16) float sH[T * 104];   // 24960 B
    __shared__ float ss[8 * T];                   // per-warp partials
    int tid = threadIdx.x;
    int wid = tid >> 5;
    int lane = tid & 31;
    int half = lane >> 4;
    int base = blockIdx.x * 256 + wid * 32;
    int va = base + (lane & 15);
    int vb = va + 16;
    bool vva = (va < VOCAB);
    bool vvb = (vb < VOCAB);

    // weight loads (once), overlap with sH staging
    u64 wa[26], wb[26];
    float boa = 0.0f, bob = 0.0f;
    if (vva) {
        const u64* wr = (const u64*)(w_out + (size_t)va * HID + half * 50);
#pragma unroll
        for (int k = 0; k < 25; k++) wa[k] = wr[k];
        if (half == 0) boa = b_out[va];
    }
    if (vvb) {
        const u64* wr = (const u64*)(w_out + (size_t)vb * HID + half * 50);
#pragma unroll
        for (int k = 0; k < 25; k++) wb[k] = wr[k];
        if (half == 0) bob = b_out[vb];
    }
    wa[25] = 0ull; wb[25] = 0ull;   // pads (match zero pads in sH)

    for (int i = tid; i < T * 104; i += LB) sH[i] = g_Hp[i];
    __syncthreads();

    for (int t = 0; t < T; t++) {
        const double2* h2 = (const double2*)(sH + t * 104 + half * 52);
        u64 a0 = f2_pack(boa, 0.0f), a1 = 0ull;
        u64 b0 = f2_pack(bob, 0.0f), b1 = 0ull;
#pragma unroll
        for (int k = 0; k < 13; k++) {
            double2 d = h2[k];
            u64 hx = (u64)__double_as_longlong(d.x);
            u64 hy = (u64)__double_as_longlong(d.y);
            ffma2(a0, wa[2 * k],     hx);
            ffma2(a1, wa[2 * k + 1], hy);
            ffma2(b0, wb[2 * k],     hx);
            ffma2(b1, wb[2 * k + 1], hy);
        }
        float pa = (f2_lo(a0) + f2_hi(a0)) + (f2_lo(a1) + f2_hi(a1));
        float pb = (f2_lo(b0) + f2_hi(b0)) + (f2_lo(b1) + f2_hi(b1));
        float la = pa + __shfl_xor_sync(0xffffffffu, pa, 16);
        float lb = pb + __shfl_xor_sync(0xffffffffu, pb, 16);
        float e = 0.0f;
        if (half == 0) {
            if (vva) e += __expf(la);
            if (vvb) e += __expf(lb);
        }
#pragma unroll
        for (int off = 8; off; off >>= 1)
            e += __shfl_down_sync(0xffffffffu, e, off);
        if (lane == 0) ss[wid * T + t] = e;
    }
    __syncthreads();
    if (tid < T) {
        float s = 0.0f;
#pragma unroll
        for (int w = 0; w < 8; w++) s += ss[w * T + tid];
        atomicAdd(&g_sumexp[tid], s);
    }
}

// ---------------- K5: token logits + final loss ----------------
__global__ void __launch_bounds__(512) k_final(const float* __restrict__ w_out,
                                               const float* __restrict__ b_out,
                                               const int* __restrict__ desc,
                                               float* __restrict__ out) {
    __shared__ float tl[T];
    __shared__ float red[16];
    int tid = threadIdx.x;
    int wid = tid >> 5;
    int lane = tid & 31;

#pragma unroll
    for (int i = 0; i < 4; i++) {
        int t = wid * 4 + i;
        if (t < T) {
            int tok = desc[t];
            const float* wr = w_out + (size_t)tok * HID;
            const float* hr = g_H + t * HID;
            float acc = wr[lane] * hr[lane]
                      + wr[lane + 32] * hr[lane + 32]
                      + wr[lane + 64] * hr[lane + 64];
            if (lane < 4) acc += wr[lane + 96] * hr[lane + 96];
#pragma unroll
            for (int off = 16; off; off >>= 1)
                acc += __shfl_down_sync(0xffffffffu, acc, off);
            if (lane == 0) tl[t] = acc + b_out[tok];
        }
    }
    __syncthreads();

    float v = 0.0f;
    if (tid < T) v = logf(g_sumexp[tid]) - tl[tid];
#pragma unroll
    for (int off = 16; off; off >>= 1)
        v += __shfl_down_sync(0xffffffffu, v, off);
    if (lane == 0) red[wid] = v;
    __syncthreads();
    if (tid == 0) out[0] = red[0] + red[1];
}

// ---------------- launch ----------------
extern "C" void kernel_launch(void* const* d_in, const int* in_sizes, int n_in,
                              void* d_out, int out_size) {
    const int*   context  = (const int*)d_in[0];
    const int*   desc     = (const int*)d_in[2];
    const float* emb_ctx  = (const float*)d_in[3];
    const float* emb_dec  = (const float*)d_in[4];
    const float* w1       = (const float*)d_in[5];
    const float* b1       = (const float*)d_in[6];
    const float* w_ih     = (const float*)d_in[7];
    const float* w_hh     = (const float*)d_in[8];
    const float* b_ih     = (const float*)d_in[9];
    const float* b_hh     = (const float*)d_in[10];
    const float* w_out    = (const float*)d_in[11];
    const float* b_out    = (const float*)d_in[12];
    float* out = (float*)d_out;

    const int rnn_smem = (T * 3 * HID + HID + 600) * (int)sizeof(float); // 74800 B
    cudaFuncSetAttribute(k_rnn, cudaFuncAttributeMaxDynamicSharedMemorySize, rnn_smem);

    k_pre<<<120, 320>>>(context, emb_ctx, desc, emb_dec, w_ih, b_ih);
    k_h0<<<HID, 256>>>(w1, b1);
    k_rnn<<<1, 600, rnn_smem>>>(w_hh, b_hh);
    k_logits<<<(VOCAB + 255) / 256, LB>>>(w_out, b_out);
    k_final<<<1, 512>>>(w_out, b_out, desc, out);
}

// round 6
// speedup vs baseline: 1.0414x; 1.0414x over previous
#include <cuda_runtime.h>
#include <math.h>

#define VOCAB 100000
#define EMB   100
#define HID   100
#define CTX   60
#define FACT  20
#define T     60

typedef unsigned long long u64;

// ---------------- scratch ----------------
__device__ float g_facts[CTX * EMB];
__device__ float g_h0[HID];
__device__ float g_gi[T * 3 * HID];
__device__ float g_H[T * HID];            // compact (k_final)
__device__ float g_Hp[T * 104];           // padded: [t][half*52 + j], pads stay 0
__device__ float g_sumexp[T];

__device__ __forceinline__ float sigmoidf_(float x) {
    return 1.0f / (1.0f + __expf(-x));
}
__device__ __forceinline__ void ffma2(u64 &d, u64 a, u64 b) {
    asm("fma.rn.f32x2 %0, %1, %2, %0;" : "+l"(d) : "l"(a), "l"(b));
}
__device__ __forceinline__ float f2_lo(u64 v) { return __int_as_float((int)(v & 0xffffffffull)); }
__device__ __forceinline__ float f2_hi(u64 v) { return __int_as_float((int)(v >> 32)); }
__device__ __forceinline__ u64 f2_pack(float x, float y) {
    return (u64)__float_as_uint(x) | ((u64)__float_as_uint(y) << 32);
}

// ---------------- K_pre: gi (blocks 0..59) + facts (blocks 60..119) ----------------
__global__ void __launch_bounds__(320) k_pre(const int* __restrict__ ctx,
                                             const float* __restrict__ emb_ctx,
                                             const int* __restrict__ desc,
                                             const float* __restrict__ emb_dec,
                                             const float* __restrict__ w_ih,
                                             const float* __restrict__ b_ih) {
    int bid = blockIdx.x;
    int j = threadIdx.x;
    if (bid < 60) {
        int t = bid;
        __shared__ __align__(16) float x[EMB];
        __shared__ int tok;
        if (j == 0) tok = (t == 0) ? 1 : desc[t - 1];
        __syncthreads();
        if (j < EMB) x[j] = emb_dec[(long)tok * EMB + j];
        __syncthreads();
        if (j < 3 * HID) {
            const float4* w4 = (const float4*)(w_ih + (long)j * EMB);
            const float4* x4 = (const float4*)x;
            float a0 = b_ih[j], a1 = 0.0f, a2 = 0.0f, a3 = 0.0f;
#pragma unroll
            for (int k = 0; k < 25; k++) {
                float4 w = w4[k];
                float4 h = x4[k];
                a0 += w.x * h.x; a1 += w.y * h.y; a2 += w.z * h.z; a3 += w.w * h.w;
            }
            g_gi[t * (3 * HID) + j] = (a0 + a1) + (a2 + a3);
        }
    } else {
        int f = bid - 60;
        if (f == 0 && j < T) g_sumexp[j] = 0.0f;
        __shared__ int toks[FACT];
        if (j < FACT) toks[j] = ctx[f * FACT + j];
        __syncthreads();
        if (j < EMB) {
            float ee = (float)j * (1.0f / 99.0f);
            float acc = 0.0f;
#pragma unroll
            for (int p = 0; p < FACT; p++) {
                float s = (float)p * (1.0f / 19.0f);
                float l = 1.0f - s - ee * (1.0f - 2.0f * s);
                acc += emb_ctx[(long)toks[p] * EMB + j] * l;
            }
            g_facts[f * EMB + j] = acc;
        }
    }
}

// ---------------- K2: h0 ----------------
__global__ void k_h0(const float* __restrict__ w1, const float* __restrict__ b1) {
    int j = blockIdx.x;
    int tid = threadIdx.x;
    const float* wr = w1 + (long)j * (CTX * HID);
    float acc = 0.0f;
    for (int k = tid; k < CTX * HID; k += 256)
        acc += g_facts[k] * wr[k];
    for (int off = 16; off; off >>= 1)
        acc += __shfl_down_sync(0xffffffffu, acc, off);
    __shared__ float s[8];
    if ((tid & 31) == 0) s[tid >> 5] = acc;
    __syncthreads();
    if (tid == 0) {
        float tot = 0.0f;
#pragma unroll
        for (int w = 0; w < 8; w++) tot += s[w];
        g_h0[j] = tot + b1[j];
    }
}

// ---------------- K3: GRU recurrence ----------------
// 320 threads (300 active dot threads). Thread `out` owns full w_hh row
// (50 u64 regs) -> gh[out] complete in-register, one STS, 2 bars/step.
__global__ void __launch_bounds__(320, 1) k_rnn(const float* __restrict__ w_hh,
                                                const float* __restrict__ b_hh) {
    extern __shared__ __align__(16) float dyn[];
    float* sgi = dyn;            // 18000
    float* h   = dyn + 18000;    // 100 (16B aligned)
    float* gh  = dyn + 18100;    // 300 (16B aligned)

    int tid = threadIdx.x;
    bool dotth = (tid < 300);

    u64 w2[50];
    float bh = 0.0f;
    if (dotth) {
        const u64* wr = (const u64*)(w_hh + (long)tid * HID);
#pragma unroll
        for (int k = 0; k < 50; k++) w2[k] = wr[k];
        bh = b_hh[tid];
    }

    for (int i = tid; i < T * 3 * HID; i += 320) sgi[i] = g_gi[i];
    if (tid < HID) h[tid] = g_h0[tid];
    __syncthreads();

    for (int t = 0; t < T; t++) {
        if (dotth) {
            const double2* h2 = (const double2*)h;
            u64 a0 = f2_pack(bh, 0.0f), a1 = 0ull;
#pragma unroll
            for (int k = 0; k < 25; k++) {
                double2 d = h2[k];
                ffma2(a0, w2[2 * k],     (u64)__double_as_longlong(d.x));
                ffma2(a1, w2[2 * k + 1], (u64)__double_as_longlong(d.y));
            }
            gh[tid] = (f2_lo(a0) + f2_hi(a0)) + (f2_lo(a1) + f2_hi(a1));
        }
        __syncthreads();

        if (tid < HID) {
            const float* gi = sgi + t * 300;
            float r = sigmoidf_(gi[tid] + gh[tid]);
            float z = sigmoidf_(gi[HID + tid] + gh[HID + tid]);
            float a = gi[2 * HID + tid] + r * gh[2 * HID + tid];
            float ex = __expf(2.0f * a);
            float n = 1.0f - __fdividef(2.0f, ex + 1.0f);
            float hn = (1.0f - z) * n + z * h[tid];
            h[tid] = hn;
            g_H[t * HID + tid] = hn;
            int idx = t * 104 + ((tid < 50) ? tid : (tid + 2));
            g_Hp[idx] = hn;
        }
        __syncthreads();
    }
}

// ---------------- K4: logits + per-step sum(exp) ----------------
// 2 vocab rows per thread (va, vb = va+16), half = lane>>4 is k-chunk.
// NO per-step shuffles except 2 xor-combines; exp partial -> exclusive smem slot.
#define LB 256
__global__ void __launch_bounds__(LB, 2) k_logits(const float* __restrict__ w_out,
                                                  const float* __restrict__ b_out) {
    extern __shared__ __align__(16) float ldyn[];
    float* sH = ldyn;                 // 60*104 = 6240 floats
    float* ss = ldyn + 6240;          // 256*61 = 15616 floats (stride 61: conflict-free)

    int tid = threadIdx.x;
    int wid = tid >> 5;
    int lane = tid & 31;
    int half = lane >> 4;
    int base = blockIdx.x * 256 + wid * 32;
    int va = base + (lane & 15);
    int vb = va + 16;
    bool vva = (va < VOCAB);
    bool vvb = (vb < VOCAB);

    // weight loads (once), overlap with sH staging
    u64 wa[26], wb[26];
    float boa = 0.0f, bob = 0.0f;
    if (vva) {
        const u64* wr = (const u64*)(w_out + (size_t)va * HID + half * 50);
#pragma unroll
        for (int k = 0; k < 25; k++) wa[k] = wr[k];
        if (half == 0) boa = b_out[va];
    }
    if (vvb) {
        const u64* wr = (const u64*)(w_out + (size_t)vb * HID + half * 50);
#pragma unroll
        for (int k = 0; k < 25; k++) wb[k] = wr[k];
        if (half == 0) bob = b_out[vb];
    }
    wa[25] = 0ull; wb[25] = 0ull;   // pads (match zero pads in sH)

    for (int i = tid; i < T * 104; i += LB) sH[i] = g_Hp[i];
    __syncthreads();

    float* myss = ss + tid * 61;
    bool myvalid = (half == 0) ? vva : vvb;

    for (int t = 0; t < T; t++) {
        const double2* h2 = (const double2*)(sH + t * 104 + half * 52);
        u64 a0 = f2_pack(boa, 0.0f), a1 = 0ull;
        u64 b0 = f2_pack(bob, 0.0f), b1 = 0ull;
#pragma unroll
        for (int k = 0; k < 13; k++) {
            double2 d = h2[k];
            u64 hx = (u64)__double_as_longlong(d.x);
            u64 hy = (u64)__double_as_longlong(d.y);
            ffma2(a0, wa[2 * k],     hx);
            ffma2(a1, wa[2 * k + 1], hy);
            ffma2(b0, wb[2 * k],     hx);
            ffma2(b1, wb[2 * k + 1], hy);
        }
        float pa = (f2_lo(a0) + f2_hi(a0)) + (f2_lo(a1) + f2_hi(a1));
        float pb = (f2_lo(b0) + f2_hi(b0)) + (f2_lo(b1) + f2_hi(b1));
        // xor exchange is symmetric: every lane ends with the full logit
        float la = pa + __shfl_xor_sync(0xffffffffu, pa, 16);
        float lb = pb + __shfl_xor_sync(0xffffffffu, pb, 16);
        float mine = (half == 0) ? la : lb;   // half0 lane owns va, half1 owns vb
        myss[t] = myvalid ? __expf(mine) : 0.0f;
    }
    __syncthreads();

    // reduction: 4 groups of 64 threads each sum 64 thread-slots per t
    {
        int g = tid >> 6;          // 0..3
        int tt = tid & 63;         // 0..63
        float s = 0.0f;
        if (tt < T) {
            const float* col = ss + (g * 64) * 61 + tt;
#pragma unroll 8
            for (int r = 0; r < 64; r++) s += col[r * 61];
        }
        __syncthreads();           // ss reads done before reusing sH? (sH distinct; just order)
        if (tt < T) sH[g * T + tt] = s;   // reuse sH region as scratch
    }
    __syncthreads();
    if (tid < T) {
        float s = sH[tid] + sH[T + tid] + sH[2 * T + tid] + sH[3 * T + tid];
        atomicAdd(&g_sumexp[tid], s);
    }
}

// ---------------- K5: token logits + final loss ----------------
__global__ void __launch_bounds__(512) k_final(const float* __restrict__ w_out,
                                               const float* __restrict__ b_out,
                                               const int* __restrict__ desc,
                                               float* __restrict__ out) {
    __shared__ float tl[T];
    __shared__ float red[16];
    int tid = threadIdx.x;
    int wid = tid >> 5;
    int lane = tid & 31;

#pragma unroll
    for (int i = 0; i < 4; i++) {
        int t = wid * 4 + i;
        if (t < T) {
            int tok = desc[t];
            const float* wr = w_out + (size_t)tok * HID;
            const float* hr = g_H + t * HID;
            float acc = wr[lane] * hr[lane]
                      + wr[lane + 32] * hr[lane + 32]
                      + wr[lane + 64] * hr[lane + 64];
            if (lane < 4) acc += wr[lane + 96] * hr[lane + 96];
#pragma unroll
            for (int off = 16; off; off >>= 1)
                acc += __shfl_down_sync(0xffffffffu, acc, off);
            if (lane == 0) tl[t] = acc + b_out[tok];
        }
    }
    __syncthreads();

    float v = 0.0f;
    if (tid < T) v = logf(g_sumexp[tid]) - tl[tid];
#pragma unroll
    for (int off = 16; off; off >>= 1)
        v += __shfl_down_sync(0xffffffffu, v, off);
    if (lane == 0) red[wid] = v;
    __syncthreads();
    if (tid == 0) out[0] = red[0] + red[1];
}

// ---------------- launch ----------------
extern "C" void kernel_launch(void* const* d_in, const int* in_sizes, int n_in,
                              void* d_out, int out_size) {
    const int*   context  = (const int*)d_in[0];
    const int*   desc     = (const int*)d_in[2];
    const float* emb_ctx  = (const float*)d_in[3];
    const float* emb_dec  = (const float*)d_in[4];
    const float* w1       = (const float*)d_in[5];
    const float* b1       = (const float*)d_in[6];
    const float* w_ih     = (const float*)d_in[7];
    const float* w_hh     = (const float*)d_in[8];
    const float* b_ih     = (const float*)d_in[9];
    const float* b_hh     = (const float*)d_in[10];
    const float* w_out    = (const float*)d_in[11];
    const float* b_out    = (const float*)d_in[12];
    float* out = (float*)d_out;

    const int rnn_smem = (T * 3 * HID + HID + 300) * (int)sizeof(float);   // 73600 B
    const int log_smem = (T * 104 + LB * 61) * (int)sizeof(float);         // 87424 B
    cudaFuncSetAttribute(k_rnn, cudaFuncAttributeMaxDynamicSharedMemorySize, rnn_smem);
    cudaFuncSetAttribute(k_logits, cudaFuncAttributeMaxDynamicSharedMemorySize, log_smem);

    k_pre<<<120, 320>>>(context, emb_ctx, desc, emb_dec, w_ih, b_ih);
    k_h0<<<HID, 256>>>(w1, b1);
    k_rnn<<<1, 320, rnn_smem>>>(w_hh, b_hh);
    k_logits<<<(VOCAB + 255) / 256, LB, log_smem>>>(w_out, b_out);
    k_final<<<1, 512>>>(w_out, b_out, desc, out);
}

// round 7
// speedup vs baseline: 1.2694x; 1.2190x over previous
#include <cuda_runtime.h>
#include <math.h>

#define VOCAB 100000
#define EMB   100
#define HID   100
#define CTX   60
#define FACT  20
#define T     60

typedef unsigned long long u64;

// ---------------- scratch ----------------
__device__ float g_facts[CTX * EMB];
__device__ float g_h0[HID];
__device__ float g_gi[T * 3 * HID];
__device__ float g_H[T * HID];
__device__ float g_sumexp[T];

__device__ __forceinline__ float sigmoidf_(float x) {
    return 1.0f / (1.0f + __expf(-x));
}
__device__ __forceinline__ void ffma2(u64 &d, u64 a, u64 b) {
    asm("fma.rn.f32x2 %0, %1, %2, %0;" : "+l"(d) : "l"(a), "l"(b));
}
__device__ __forceinline__ float f2_lo(u64 v) { return __int_as_float((int)(v & 0xffffffffull)); }
__device__ __forceinline__ float f2_hi(u64 v) { return __int_as_float((int)(v >> 32)); }
__device__ __forceinline__ u64 f2_pack(float x, float y) {
    return (u64)__float_as_uint(x) | ((u64)__float_as_uint(y) << 32);
}
__device__ __forceinline__ unsigned to_tf32(float f) {
    unsigned r;
    asm("cvt.rna.tf32.f32 %0, %1;" : "=r"(r) : "f"(f));
    return r;
}
__device__ __forceinline__ void mma_tf32(float* c, const unsigned* a, const unsigned* b) {
    asm volatile(
        "mma.sync.aligned.m16n8k8.row.col.f32.tf32.tf32.f32 "
        "{%0,%1,%2,%3}, {%4,%5,%6,%7}, {%8,%9}, {%0,%1,%2,%3};"
        : "+f"(c[0]), "+f"(c[1]), "+f"(c[2]), "+f"(c[3])
        : "r"(a[0]), "r"(a[1]), "r"(a[2]), "r"(a[3]), "r"(b[0]), "r"(b[1]));
}

// ---------------- K_pre: gi (blocks 0..59) + facts (blocks 60..119) ----------------
__global__ void __launch_bounds__(320) k_pre(const int* __restrict__ ctx,
                                             const float* __restrict__ emb_ctx,
                                             const int* __restrict__ desc,
                                             const float* __restrict__ emb_dec,
                                             const float* __restrict__ w_ih,
                                             const float* __restrict__ b_ih) {
    int bid = blockIdx.x;
    int j = threadIdx.x;
    if (bid < 60) {
        int t = bid;
        __shared__ __align__(16) float x[EMB];
        __shared__ int tok;
        if (j == 0) tok = (t == 0) ? 1 : desc[t - 1];
        __syncthreads();
        if (j < EMB) x[j] = emb_dec[(long)tok * EMB + j];
        __syncthreads();
        if (j < 3 * HID) {
            const float4* w4 = (const float4*)(w_ih + (long)j * EMB);
            const float4* x4 = (const float4*)x;
            float a0 = b_ih[j], a1 = 0.0f, a2 = 0.0f, a3 = 0.0f;
#pragma unroll
            for (int k = 0; k < 25; k++) {
                float4 w = w4[k];
                float4 h = x4[k];
                a0 += w.x * h.x; a1 += w.y * h.y; a2 += w.z * h.z; a3 += w.w * h.w;
            }
            g_gi[t * (3 * HID) + j] = (a0 + a1) + (a2 + a3);
        }
    } else {
        int f = bid - 60;
        if (f == 0 && j < T) g_sumexp[j] = 0.0f;
        __shared__ int toks[FACT];
        if (j < FACT) toks[j] = ctx[f * FACT + j];
        __syncthreads();
        if (j < EMB) {
            float ee = (float)j * (1.0f / 99.0f);
            float acc = 0.0f;
#pragma unroll
            for (int p = 0; p < FACT; p++) {
                float s = (float)p * (1.0f / 19.0f);
                float l = 1.0f - s - ee * (1.0f - 2.0f * s);
                acc += emb_ctx[(long)toks[p] * EMB + j] * l;
            }
            g_facts[f * EMB + j] = acc;
        }
    }
}

// ---------------- K2: h0 ----------------
__global__ void k_h0(const float* __restrict__ w1, const float* __restrict__ b1) {
    int j = blockIdx.x;
    int tid = threadIdx.x;
    const float* wr = w1 + (long)j * (CTX * HID);
    float acc = 0.0f;
    for (int k = tid; k < CTX * HID; k += 256)
        acc += g_facts[k] * wr[k];
    for (int off = 16; off; off >>= 1)
        acc += __shfl_down_sync(0xffffffffu, acc, off);
    __shared__ float s[8];
    if ((tid & 31) == 0) s[tid >> 5] = acc;
    __syncthreads();
    if (tid == 0) {
        float tot = 0.0f;
#pragma unroll
        for (int w = 0; w < 8; w++) tot += s[w];
        g_h0[j] = tot + b1[j];
    }
}

// ---------------- K3: GRU recurrence (block 0) + L2 prefetch (blocks 1..147) ----------------
// Block 0: 600 threads, out = tid%300, half = tid/300; gi in smem, 2 bars/step.
__global__ void __launch_bounds__(600, 1) k_rnn(const float* __restrict__ w_hh,
                                                const float* __restrict__ b_hh,
                                                const float* __restrict__ w_out,
                                                const float* __restrict__ b_out) {
    if (blockIdx.x != 0) {
        // warm L2 with w_out + b_out while block 0 runs the recurrence
        int pid = (blockIdx.x - 1) * 600 + threadIdx.x;   // 0..88199
        const float4* w4 = (const float4*)w_out;          // 2,500,000 float4
        float ax = 0.0f, ay = 0.0f, az = 0.0f, aw = 0.0f;
        for (int i = pid; i < (VOCAB * HID) / 4; i += 88200) {
            float4 v = __ldg(&w4[i]);
            ax += v.x; ay += v.y; az += v.z; aw += v.w;
        }
        const float4* b4 = (const float4*)b_out;          // 25,000 float4
        for (int i = pid; i < VOCAB / 4; i += 88200) {
            float4 v = __ldg(&b4[i]);
            ax += v.x; ay += v.y; az += v.z; aw += v.w;
        }
        float s = (ax + ay) + (az + aw);
        if (s == 1.23456789e30f) g_facts[0] = s;   // never true; defeats DCE
        return;
    }

    extern __shared__ __align__(16) float dyn[];
    float* sgi = dyn;            // 18000
    float* h   = dyn + 18000;    // 100
    float* ps  = h + 100;        // 600

    int tid = threadIdx.x;
    int out = tid % 300;
    int half = tid / 300;

    u64 w2[25];
    {
        const u64* wr = (const u64*)(w_hh + (long)out * HID + half * 50);
#pragma unroll
        for (int k = 0; k < 25; k++) w2[k] = wr[k];
    }
    float bhr = 0.0f, bhz = 0.0f, bhn = 0.0f;
    if (tid < HID) {
        bhr = b_hh[tid];
        bhz = b_hh[HID + tid];
        bhn = b_hh[2 * HID + tid];
    }

    for (int i = tid; i < T * 3 * HID; i += 600) sgi[i] = g_gi[i];
    if (tid < HID) h[tid] = g_h0[tid];
    __syncthreads();

    for (int t = 0; t < T; t++) {
        {
            const u64* h2 = (const u64*)(h + half * 50);
            u64 a0 = 0ull, a1 = 0ull;
#pragma unroll
            for (int k = 0; k < 12; k++) {
                ffma2(a0, w2[2 * k], h2[2 * k]);
                ffma2(a1, w2[2 * k + 1], h2[2 * k + 1]);
            }
            ffma2(a0, w2[24], h2[24]);
            ps[tid] = (f2_lo(a0) + f2_hi(a0)) + (f2_lo(a1) + f2_hi(a1));
        }
        __syncthreads();

        if (tid < HID) {
            float ghr = ps[tid]       + ps[tid + 300] + bhr;
            float ghz = ps[tid + 100] + ps[tid + 400] + bhz;
            float ghn = ps[tid + 200] + ps[tid + 500] + bhn;
            const float* gi = sgi + t * 300;
            float r = sigmoidf_(gi[tid] + ghr);
            float z = sigmoidf_(gi[HID + tid] + ghz);
            float a = gi[2 * HID + tid] + r * ghn;
            float ex = __expf(2.0f * a);
            float n = 1.0f - __fdividef(2.0f, ex + 1.0f);
            float hn = (1.0f - z) * n + z * h[tid];
            h[tid] = hn;
            g_H[t * HID + tid] = hn;
        }
        __syncthreads();
    }
}

// ---------------- K4: logits via tf32 mma + fused exp-sum epilogue ----------------
// Block: 256 thr (8 warps), N-tile 256 vocab rows (warp owns 32), M=64 (60 pad), K=104.
// smem (floats): sA 64*108, sB 256*108, sBias 256, sSum 64*8.
#define SA_OFF   0
#define SB_OFF   (64 * 108)
#define SBIAS_OFF (SB_OFF + 256 * 108)
#define SSUM_OFF  (SBIAS_OFF + 256)
#define SMEM_FLOATS (SSUM_OFF + 64 * 8)

__global__ void __launch_bounds__(256, 1) k_logits_mma(const float* __restrict__ w_out,
                                                       const float* __restrict__ b_out) {
    extern __shared__ __align__(16) float ldyn[];
    float* sA = ldyn + SA_OFF;
    float* sB = ldyn + SB_OFF;
    float* sBias = ldyn + SBIAS_OFF;
    float* sSum = ldyn + SSUM_OFF;

    int tid = threadIdx.x;
    int N0 = blockIdx.x * 256;
    int valid_n = VOCAB - N0; if (valid_n > 256) valid_n = 256;

    // ---- stage A (H, tf32, zero-padded to 64x108) ----
    for (int i = tid; i < 64 * 108; i += 256) {
        int m = i / 108, k = i - m * 108;
        float v = (m < T && k < HID) ? g_H[m * HID + k] : 0.0f;
        sA[i] = __uint_as_float(to_tf32(v));
    }
    // ---- stage B (w_out tile, tf32) ----
    for (int i = tid; i < 256 * HID; i += 256) {
        int n = i / HID, k = i - n * HID;
        float v = (n < valid_n) ? w_out[(size_t)N0 * HID + i] : 0.0f;
        sB[n * 108 + k] = __uint_as_float(to_tf32(v));
    }
    for (int i = tid; i < 256 * 8; i += 256)
        sB[(i >> 3) * 108 + HID + (i & 7)] = 0.0f;
    if (tid < 256)
        sBias[tid] = (tid < valid_n) ? b_out[N0 + tid] : -1e30f;
    __syncthreads();

    int warp = tid >> 5;
    int lane = tid & 31;
    int grp = lane >> 2;     // 0..7
    int qi = lane & 3;       // 0..3

    float c[4][4][4];
#pragma unroll
    for (int mi = 0; mi < 4; mi++)
#pragma unroll
        for (int nf = 0; nf < 4; nf++)
#pragma unroll
            for (int r = 0; r < 4; r++) c[mi][nf][r] = 0.0f;

#pragma unroll 1
    for (int kt = 0; kt < 13; kt++) {
        int k0 = kt * 8 + qi;
        unsigned a[4][4];
#pragma unroll
        for (int mi = 0; mi < 4; mi++) {
            int r0 = (grp + 16 * mi) * 108 + k0;
            a[mi][0] = __float_as_uint(sA[r0]);
            a[mi][1] = __float_as_uint(sA[r0 + 8 * 108]);
            a[mi][2] = __float_as_uint(sA[r0 + 4]);
            a[mi][3] = __float_as_uint(sA[r0 + 8 * 108 + 4]);
        }
        unsigned b[4][2];
#pragma unroll
        for (int nf = 0; nf < 4; nf++) {
            int nc = (warp * 32 + nf * 8 + grp) * 108 + k0;
            b[nf][0] = __float_as_uint(sB[nc]);
            b[nf][1] = __float_as_uint(sB[nc + 4]);
        }
#pragma unroll
        for (int mi = 0; mi < 4; mi++)
#pragma unroll
            for (int nf = 0; nf < 4; nf++)
                mma_tf32(c[mi][nf], a[mi], b[nf]);
    }

    // ---- epilogue: exp + row sums ----
    float rowsum[8];
#pragma unroll
    for (int j = 0; j < 8; j++) rowsum[j] = 0.0f;
#pragma unroll
    for (int nf = 0; nf < 4; nf++) {
        int n0 = warp * 32 + nf * 8 + 2 * qi;
        float bias0 = sBias[n0];
        float bias1 = sBias[n0 + 1];
#pragma unroll
        for (int mi = 0; mi < 4; mi++) {
            float e00 = __expf(c[mi][nf][0] + bias0);
            float e01 = __expf(c[mi][nf][1] + bias1);
            float e10 = __expf(c[mi][nf][2] + bias0);
            float e11 = __expf(c[mi][nf][3] + bias1);
            rowsum[mi * 2]     += e00 + e01;   // row grp + 16*mi
            rowsum[mi * 2 + 1] += e10 + e11;   // row grp + 8 + 16*mi
        }
    }
    // reduce across the 4 lanes of each group (same rows, different cols)
#pragma unroll
    for (int j = 0; j < 8; j++) {
        rowsum[j] += __shfl_xor_sync(0xffffffffu, rowsum[j], 1);
        rowsum[j] += __shfl_xor_sync(0xffffffffu, rowsum[j], 2);
    }
    if (qi == 0) {
#pragma unroll
        for (int j = 0; j < 8; j++) {
            int row = grp + 8 * (j & 1) + 16 * (j >> 1);
            sSum[row * 8 + warp] = rowsum[j];
        }
    }
    __syncthreads();
    if (tid < 64) {
        float s = 0.0f;
#pragma unroll
        for (int w = 0; w < 8; w++) s += sSum[tid * 8 + w];
        if (tid < T) atomicAdd(&g_sumexp[tid], s);
    }
}

// ---------------- K5: token logits + final loss ----------------
__global__ void __launch_bounds__(512) k_final(const float* __restrict__ w_out,
                                               const float* __restrict__ b_out,
                                               const int* __restrict__ desc,
                                               float* __restrict__ out) {
    __shared__ float tl[T];
    __shared__ float red[16];
    int tid = threadIdx.x;
    int wid = tid >> 5;
    int lane = tid & 31;

#pragma unroll
    for (int i = 0; i < 4; i++) {
        int t = wid * 4 + i;
        if (t < T) {
            int tok = desc[t];
            const float* wr = w_out + (size_t)tok * HID;
            const float* hr = g_H + t * HID;
            float acc = wr[lane] * hr[lane]
                      + wr[lane + 32] * hr[lane + 32]
                      + wr[lane + 64] * hr[lane + 64];
            if (lane < 4) acc += wr[lane + 96] * hr[lane + 96];
#pragma unroll
            for (int off = 16; off; off >>= 1)
                acc += __shfl_down_sync(0xffffffffu, acc, off);
            if (lane == 0) tl[t] = acc + b_out[tok];
        }
    }
    __syncthreads();

    float v = 0.0f;
    if (tid < T) v = logf(g_sumexp[tid]) - tl[tid];
#pragma unroll
    for (int off = 16; off; off >>= 1)
        v += __shfl_down_sync(0xffffffffu, v, off);
    if (lane == 0) red[wid] = v;
    __syncthreads();
    if (tid == 0) out[0] = red[0] + red[1];
}

// ---------------- launch ----------------
extern "C" void kernel_launch(void* const* d_in, const int* in_sizes, int n_in,
                              void* d_out, int out_size) {
    const int*   context  = (const int*)d_in[0];
    const int*   desc     = (const int*)d_in[2];
    const float* emb_ctx  = (const float*)d_in[3];
    const float* emb_dec  = (const float*)d_in[4];
    const float* w1       = (const float*)d_in[5];
    const float* b1       = (const float*)d_in[6];
    const float* w_ih     = (const float*)d_in[7];
    const float* w_hh     = (const float*)d_in[8];
    const float* b_ih     = (const float*)d_in[9];
    const float* b_hh     = (const float*)d_in[10];
    const float* w_out    = (const float*)d_in[11];
    const float* b_out    = (const float*)d_in[12];
    float* out = (float*)d_out;

    const int rnn_smem = (T * 3 * HID + HID + 600) * (int)sizeof(float);   // 74800 B
    const int mma_smem = SMEM_FLOATS * (int)sizeof(float);                 // 141312 B
    cudaFuncSetAttribute(k_rnn, cudaFuncAttributeMaxDynamicSharedMemorySize, rnn_smem);
    cudaFuncSetAttribute(k_logits_mma, cudaFuncAttributeMaxDynamicSharedMemorySize, mma_smem);

    k_pre<<<120, 320>>>(context, emb_ctx, desc, emb_dec, w_ih, b_ih);
    k_h0<<<HID, 256>>>(w1, b1);
    k_rnn<<<148, 600, rnn_smem>>>(w_hh, b_hh, w_out, b_out);
    k_logits_mma<<<(VOCAB + 255) / 256, 256, mma_smem>>>(w_out, b_out);
    k_final<<<1, 512>>>(w_out, b_out, desc, out);
}

// round 8
// speedup vs baseline: 1.4679x; 1.1564x over previous
#include <cuda_runtime.h>
#include <math.h>

#define VOCAB 100000
#define EMB   100
#define HID   100
#define CTX   60
#define FACT  20
#define T     60

typedef unsigned long long u64;

// ---------------- scratch ----------------
__device__ float g_facts[CTX * EMB];
__device__ float g_h0[HID];
__device__ float g_gi[T * 3 * HID];
__device__ float g_H[T * HID];
__device__ float g_sumexp[T];

__device__ __forceinline__ float sigmoidf_(float x) {
    return 1.0f / (1.0f + __expf(-x));
}
__device__ __forceinline__ void ffma2(u64 &d, u64 a, u64 b) {
    asm("fma.rn.f32x2 %0, %1, %2, %0;" : "+l"(d) : "l"(a), "l"(b));
}
__device__ __forceinline__ float f2_lo(u64 v) { return __int_as_float((int)(v & 0xffffffffull)); }
__device__ __forceinline__ float f2_hi(u64 v) { return __int_as_float((int)(v >> 32)); }
__device__ __forceinline__ unsigned to_tf32(float f) {
    unsigned r;
    asm("cvt.rna.tf32.f32 %0, %1;" : "=r"(r) : "f"(f));
    return r;
}
__device__ __forceinline__ void mma_tf32(float* c, const unsigned* a, const unsigned* b) {
    asm volatile(
        "mma.sync.aligned.m16n8k8.row.col.f32.tf32.tf32.f32 "
        "{%0,%1,%2,%3}, {%4,%5,%6,%7}, {%8,%9}, {%0,%1,%2,%3};"
        : "+f"(c[0]), "+f"(c[1]), "+f"(c[2]), "+f"(c[3])
        : "r"(a[0]), "r"(a[1]), "r"(a[2]), "r"(a[3]), "r"(b[0]), "r"(b[1]));
}

// ---------------- K_pre: gi (blocks 0..59) + facts (blocks 60..119) ----------------
__global__ void __launch_bounds__(320) k_pre(const int* __restrict__ ctx,
                                             const float* __restrict__ emb_ctx,
                                             const int* __restrict__ desc,
                                             const float* __restrict__ emb_dec,
                                             const float* __restrict__ w_ih,
                                             const float* __restrict__ b_ih) {
    int bid = blockIdx.x;
    int j = threadIdx.x;
    if (bid < 60) {
        int t = bid;
        __shared__ __align__(16) float x[EMB];
        __shared__ int tok;
        if (j == 0) tok = (t == 0) ? 1 : desc[t - 1];
        __syncthreads();
        if (j < EMB) x[j] = emb_dec[(long)tok * EMB + j];
        __syncthreads();
        if (j < 3 * HID) {
            const float4* w4 = (const float4*)(w_ih + (long)j * EMB);
            const float4* x4 = (const float4*)x;
            float a0 = b_ih[j], a1 = 0.0f, a2 = 0.0f, a3 = 0.0f;
#pragma unroll
            for (int k = 0; k < 25; k++) {
                float4 w = w4[k];
                float4 h = x4[k];
                a0 += w.x * h.x; a1 += w.y * h.y; a2 += w.z * h.z; a3 += w.w * h.w;
            }
            g_gi[t * (3 * HID) + j] = (a0 + a1) + (a2 + a3);
        }
    } else {
        int f = bid - 60;
        if (f == 0 && j < T) g_sumexp[j] = 0.0f;
        __shared__ int toks[FACT];
        if (j < FACT) toks[j] = ctx[f * FACT + j];
        __syncthreads();
        if (j < EMB) {
            float ee = (float)j * (1.0f / 99.0f);
            float acc = 0.0f;
#pragma unroll
            for (int p = 0; p < FACT; p++) {
                float s = (float)p * (1.0f / 19.0f);
                float l = 1.0f - s - ee * (1.0f - 2.0f * s);
                acc += emb_ctx[(long)toks[p] * EMB + j] * l;
            }
            g_facts[f * EMB + j] = acc;
        }
    }
}

// ---------------- K2: h0 ----------------
__global__ void k_h0(const float* __restrict__ w1, const float* __restrict__ b1) {
    int j = blockIdx.x;
    int tid = threadIdx.x;
    const float* wr = w1 + (long)j * (CTX * HID);
    float acc = 0.0f;
    for (int k = tid; k < CTX * HID; k += 256)
        acc += g_facts[k] * wr[k];
    for (int off = 16; off; off >>= 1)
        acc += __shfl_down_sync(0xffffffffu, acc, off);
    __shared__ float s[8];
    if ((tid & 31) == 0) s[tid >> 5] = acc;
    __syncthreads();
    if (tid == 0) {
        float tot = 0.0f;
#pragma unroll
        for (int w = 0; w < 8; w++) tot += s[w];
        g_h0[j] = tot + b1[j];
    }
}

// ---------------- K3: GRU recurrence (block 0) + L2 prefetch (blocks 1..147) ----------------
__global__ void __launch_bounds__(600, 1) k_rnn(const float* __restrict__ w_hh,
                                                const float* __restrict__ b_hh,
                                                const float* __restrict__ w_out,
                                                const float* __restrict__ b_out) {
    if (blockIdx.x != 0) {
        int pid = (blockIdx.x - 1) * 600 + threadIdx.x;
        const float4* w4 = (const float4*)w_out;
        float ax = 0.0f, ay = 0.0f, az = 0.0f, aw = 0.0f;
        for (int i = pid; i < (VOCAB * HID) / 4; i += 88200) {
            float4 v = __ldg(&w4[i]);
            ax += v.x; ay += v.y; az += v.z; aw += v.w;
        }
        const float4* b4 = (const float4*)b_out;
        for (int i = pid; i < VOCAB / 4; i += 88200) {
            float4 v = __ldg(&b4[i]);
            ax += v.x; ay += v.y; az += v.z; aw += v.w;
        }
        float s = (ax + ay) + (az + aw);
        if (s == 1.23456789e30f) g_facts[0] = s;   // defeats DCE, never true
        return;
    }

    extern __shared__ __align__(16) float dyn[];
    float* sgi = dyn;            // 18000
    float* h   = dyn + 18000;    // 100
    float* ps  = h + 100;        // 600

    int tid = threadIdx.x;
    int out = tid % 300;
    int half = tid / 300;

    u64 w2[25];
    {
        const u64* wr = (const u64*)(w_hh + (long)out * HID + half * 50);
#pragma unroll
        for (int k = 0; k < 25; k++) w2[k] = wr[k];
    }
    float bhr = 0.0f, bhz = 0.0f, bhn = 0.0f;
    if (tid < HID) {
        bhr = b_hh[tid];
        bhz = b_hh[HID + tid];
        bhn = b_hh[2 * HID + tid];
    }

    for (int i = tid; i < T * 3 * HID; i += 600) sgi[i] = g_gi[i];
    if (tid < HID) h[tid] = g_h0[tid];
    __syncthreads();

    for (int t = 0; t < T; t++) {
        {
            const u64* h2 = (const u64*)(h + half * 50);
            u64 a0 = 0ull, a1 = 0ull;
#pragma unroll
            for (int k = 0; k < 12; k++) {
                ffma2(a0, w2[2 * k], h2[2 * k]);
                ffma2(a1, w2[2 * k + 1], h2[2 * k + 1]);
            }
            ffma2(a0, w2[24], h2[24]);
            ps[tid] = (f2_lo(a0) + f2_hi(a0)) + (f2_lo(a1) + f2_hi(a1));
        }
        __syncthreads();

        if (tid < HID) {
            float ghr = ps[tid]       + ps[tid + 300] + bhr;
            float ghz = ps[tid + 100] + ps[tid + 400] + bhz;
            float ghn = ps[tid + 200] + ps[tid + 500] + bhn;
            const float* gi = sgi + t * 300;
            float r = sigmoidf_(gi[tid] + ghr);
            float z = sigmoidf_(gi[HID + tid] + ghz);
            float a = gi[2 * HID + tid] + r * ghn;
            float ex = __expf(2.0f * a);
            float n = 1.0f - __fdividef(2.0f, ex + 1.0f);
            float hn = (1.0f - z) * n + z * h[tid];
            h[tid] = hn;
            g_H[t * HID + tid] = hn;
        }
        __syncthreads();
    }
}

// ---------------- K4: logits via tf32 mma, N-tile 128, 2 blocks/SM ----------------
// 256 thr (8 warps), warp owns 16 cols (2 n-frags), M=64 (4 m-frags), K=104 (13 steps).
// smem floats: sA 64*108, sB 128*108, sBias 128, sSum 64*8  -> 85504 B
#define SA_F   (64 * 108)
#define SB_F   (128 * 108)
#define SMEM_FLOATS (SA_F + SB_F + 128 + 64 * 8)

__global__ void __launch_bounds__(256, 2) k_logits_mma(const float* __restrict__ w_out,
                                                       const float* __restrict__ b_out) {
    extern __shared__ __align__(16) float ldyn[];
    float* sA = ldyn;
    float* sB = sA + SA_F;
    float* sBias = sB + SB_F;
    float* sSum = sBias + 128;

    int tid = threadIdx.x;
    int N0 = blockIdx.x * 128;
    int valid_n = VOCAB - N0; if (valid_n > 128) valid_n = 128;

    // ---- stage B first (big, raw fp32 bits -> tf32 by truncation), float4 ----
    {
        const float4* wg = (const float4*)(w_out + (size_t)N0 * HID);   // i = n*25 + k4
        float4 z4 = make_float4(0.f, 0.f, 0.f, 0.f);
        for (int i = tid; i < 128 * 25; i += 256) {
            int n = i / 25;
            int k4 = i - n * 25;
            float4 v = (n < valid_n) ? wg[i] : z4;
            *(float4*)(sB + n * 108 + k4 * 4) = v;
        }
        // pad k = 100..107
        for (int i = tid; i < 128 * 2; i += 256)
            *(float4*)(sB + (i >> 1) * 108 + 100 + (i & 1) * 4) = z4;
    }
    // ---- stage A (H, RNA tf32, zero-padded 64x108): 4 threads/row ----
    {
        int m = tid >> 2;
        const float* hr = g_H + m * HID;
        bool mv = (m < T);
        for (int k = (tid & 3); k < 108; k += 4) {
            float v = (mv && k < HID) ? hr[k] : 0.0f;
            sA[m * 108 + k] = __uint_as_float(to_tf32(v));
        }
    }
    if (tid < 128)
        sBias[tid] = (tid < valid_n) ? b_out[N0 + tid] : -1e30f;
    __syncthreads();

    int warp = tid >> 5;
    int lane = tid & 31;
    int grp = lane >> 2;     // 0..7
    int qi = lane & 3;       // 0..3

    const float* aptr = sA + grp * 108 + qi;
    const float* bptr = sB + (warp * 16 + grp) * 108 + qi;

    float c[4][2][4];
#pragma unroll
    for (int mi = 0; mi < 4; mi++)
#pragma unroll
        for (int nf = 0; nf < 2; nf++)
#pragma unroll
            for (int r = 0; r < 4; r++) c[mi][nf][r] = 0.0f;

#pragma unroll
    for (int kt = 0; kt < 13; kt++) {
        int k0 = kt * 8;
        unsigned a[4][4];
#pragma unroll
        for (int mi = 0; mi < 4; mi++) {
            const float* p = aptr + mi * 16 * 108 + k0;
            a[mi][0] = __float_as_uint(p[0]);
            a[mi][1] = __float_as_uint(p[8 * 108]);
            a[mi][2] = __float_as_uint(p[4]);
            a[mi][3] = __float_as_uint(p[8 * 108 + 4]);
        }
        unsigned b[2][2];
#pragma unroll
        for (int nf = 0; nf < 2; nf++) {
            const float* p = bptr + nf * 8 * 108 + k0;
            b[nf][0] = __float_as_uint(p[0]);
            b[nf][1] = __float_as_uint(p[4]);
        }
#pragma unroll
        for (int mi = 0; mi < 4; mi++)
#pragma unroll
            for (int nf = 0; nf < 2; nf++)
                mma_tf32(c[mi][nf], a[mi], b[nf]);
    }

    // ---- epilogue: exp + row sums ----
    float rowsum[8];
#pragma unroll
    for (int j = 0; j < 8; j++) rowsum[j] = 0.0f;
#pragma unroll
    for (int nf = 0; nf < 2; nf++) {
        int n0 = warp * 16 + nf * 8 + 2 * qi;
        float bias0 = sBias[n0];
        float bias1 = sBias[n0 + 1];
#pragma unroll
        for (int mi = 0; mi < 4; mi++) {
            rowsum[mi * 2]     += __expf(c[mi][nf][0] + bias0) + __expf(c[mi][nf][1] + bias1);
            rowsum[mi * 2 + 1] += __expf(c[mi][nf][2] + bias0) + __expf(c[mi][nf][3] + bias1);
        }
    }
#pragma unroll
    for (int j = 0; j < 8; j++) {
        rowsum[j] += __shfl_xor_sync(0xffffffffu, rowsum[j], 1);
        rowsum[j] += __shfl_xor_sync(0xffffffffu, rowsum[j], 2);
    }
    if (qi == 0) {
#pragma unroll
        for (int j = 0; j < 8; j++) {
            int row = grp + 8 * (j & 1) + 16 * (j >> 1);
            sSum[row * 8 + warp] = rowsum[j];
        }
    }
    __syncthreads();
    if (tid < 64) {
        float s = 0.0f;
#pragma unroll
        for (int w = 0; w < 8; w++) s += sSum[tid * 8 + w];
        if (tid < T) atomicAdd(&g_sumexp[tid], s);
    }
}

// ---------------- K5: token logits + final loss ----------------
__global__ void __launch_bounds__(512) k_final(const float* __restrict__ w_out,
                                               const float* __restrict__ b_out,
                                               const int* __restrict__ desc,
                                               float* __restrict__ out) {
    __shared__ float tl[T];
    __shared__ float red[16];
    int tid = threadIdx.x;
    int wid = tid >> 5;
    int lane = tid & 31;

#pragma unroll
    for (int i = 0; i < 4; i++) {
        int t = wid * 4 + i;
        if (t < T) {
            int tok = desc[t];
            const float* wr = w_out + (size_t)tok * HID;
            const float* hr = g_H + t * HID;
            float acc = wr[lane] * hr[lane]
                      + wr[lane + 32] * hr[lane + 32]
                      + wr[lane + 64] * hr[lane + 64];
            if (lane < 4) acc += wr[lane + 96] * hr[lane + 96];
#pragma unroll
            for (int off = 16; off; off >>= 1)
                acc += __shfl_down_sync(0xffffffffu, acc, off);
            if (lane == 0) tl[t] = acc + b_out[tok];
        }
    }
    __syncthreads();

    float v = 0.0f;
    if (tid < T) v = logf(g_sumexp[tid]) - tl[tid];
#pragma unroll
    for (int off = 16; off; off >>= 1)
        v += __shfl_down_sync(0xffffffffu, v, off);
    if (lane == 0) red[wid] = v;
    __syncthreads();
    if (tid == 0) out[0] = red[0] + red[1];
}

// ---------------- launch ----------------
extern "C" void kernel_launch(void* const* d_in, const int* in_sizes, int n_in,
                              void* d_out, int out_size) {
    const int*   context  = (const int*)d_in[0];
    const int*   desc     = (const int*)d_in[2];
    const float* emb_ctx  = (const float*)d_in[3];
    const float* emb_dec  = (const float*)d_in[4];
    const float* w1       = (const float*)d_in[5];
    const float* b1       = (const float*)d_in[6];
    const float* w_ih     = (const float*)d_in[7];
    const float* w_hh     = (const float*)d_in[8];
    const float* b_ih     = (const float*)d_in[9];
    const float* b_hh     = (const float*)d_in[10];
    const float* w_out    = (const float*)d_in[11];
    const float* b_out    = (const float*)d_in[12];
    float* out = (float*)d_out;

    const int rnn_smem = (T * 3 * HID + HID + 600) * (int)sizeof(float);   // 74800 B
    const int mma_smem = SMEM_FLOATS * (int)sizeof(float);                 // 85504 B
    cudaFuncSetAttribute(k_rnn, cudaFuncAttributeMaxDynamicSharedMemorySize, rnn_smem);
    cudaFuncSetAttribute(k_logits_mma, cudaFuncAttributeMaxDynamicSharedMemorySize, mma_smem);

    k_pre<<<120, 320>>>(context, emb_ctx, desc, emb_dec, w_ih, b_ih);
    k_h0<<<HID, 256>>>(w1, b1);
    k_rnn<<<148, 600, rnn_smem>>>(w_hh, b_hh, w_out, b_out);
    k_logits_mma<<<(VOCAB + 127) / 128, 256, mma_smem>>>(w_out, b_out);
    k_final<<<1, 512>>>(w_out, b_out, desc, out);
}

// round 9
// speedup vs baseline: 1.5225x; 1.0372x over previous
#include <cuda_runtime.h>
#include <math.h>

#define VOCAB 100000
#define EMB   100
#define HID   100
#define CTX   60
#define FACT  20
#define T     60
#define NTILES 782        // ceil(100000 / 128)
#define PGRID  148

typedef unsigned long long u64;
typedef unsigned int u32;

// ---------------- scratch ----------------
__device__ float g_facts[CTX * EMB];
__device__ float g_h0[HID];
__device__ float g_gi[T * 3 * HID];
__device__ float g_H[T * HID];
__device__ float g_sumexp[T];

__device__ __forceinline__ float sigmoidf_(float x) {
    return 1.0f / (1.0f + __expf(-x));
}
__device__ __forceinline__ void ffma2(u64 &d, u64 a, u64 b) {
    asm("fma.rn.f32x2 %0, %1, %2, %0;" : "+l"(d) : "l"(a), "l"(b));
}
__device__ __forceinline__ float f2_lo(u64 v) { return __int_as_float((int)(v & 0xffffffffull)); }
__device__ __forceinline__ float f2_hi(u64 v) { return __int_as_float((int)(v >> 32)); }
__device__ __forceinline__ unsigned to_tf32(float f) {
    unsigned r;
    asm("cvt.rna.tf32.f32 %0, %1;" : "=r"(r) : "f"(f));
    return r;
}
__device__ __forceinline__ void mma_tf32(float* c, const unsigned* a, const unsigned* b) {
    asm volatile(
        "mma.sync.aligned.m16n8k8.row.col.f32.tf32.tf32.f32 "
        "{%0,%1,%2,%3}, {%4,%5,%6,%7}, {%8,%9}, {%0,%1,%2,%3};"
        : "+f"(c[0]), "+f"(c[1]), "+f"(c[2]), "+f"(c[3])
        : "r"(a[0]), "r"(a[1]), "r"(a[2]), "r"(a[3]), "r"(b[0]), "r"(b[1]));
}
__device__ __forceinline__ u32 s2u(const void* p) {
    return (u32)__cvta_generic_to_shared(p);
}
__device__ __forceinline__ void cp_async16(u32 dst, const void* src) {
    asm volatile("cp.async.cg.shared.global [%0], [%1], 16;" :: "r"(dst), "l"(src));
}
__device__ __forceinline__ void cp_commit() {
    asm volatile("cp.async.commit_group;");
}
__device__ __forceinline__ void cp_wait1() {
    asm volatile("cp.async.wait_group 1;");
}
__device__ __forceinline__ void ldsm_x4(unsigned* r, u32 addr) {
    asm volatile("ldmatrix.sync.aligned.m8n8.x4.shared.b16 {%0,%1,%2,%3}, [%4];"
                 : "=r"(r[0]), "=r"(r[1]), "=r"(r[2]), "=r"(r[3]) : "r"(addr));
}

// ---------------- K_pre: gi (blocks 0..59) + facts (blocks 60..119) ----------------
__global__ void __launch_bounds__(320) k_pre(const int* __restrict__ ctx,
                                             const float* __restrict__ emb_ctx,
                                             const int* __restrict__ desc,
                                             const float* __restrict__ emb_dec,
                                             const float* __restrict__ w_ih,
                                             const float* __restrict__ b_ih) {
    int bid = blockIdx.x;
    int j = threadIdx.x;
    if (bid < 60) {
        int t = bid;
        __shared__ __align__(16) float x[EMB];
        __shared__ int tok;
        if (j == 0) tok = (t == 0) ? 1 : desc[t - 1];
        __syncthreads();
        if (j < EMB) x[j] = emb_dec[(long)tok * EMB + j];
        __syncthreads();
        if (j < 3 * HID) {
            const float4* w4 = (const float4*)(w_ih + (long)j * EMB);
            const float4* x4 = (const float4*)x;
            float a0 = b_ih[j], a1 = 0.0f, a2 = 0.0f, a3 = 0.0f;
#pragma unroll
            for (int k = 0; k < 25; k++) {
                float4 w = w4[k];
                float4 h = x4[k];
                a0 += w.x * h.x; a1 += w.y * h.y; a2 += w.z * h.z; a3 += w.w * h.w;
            }
            g_gi[t * (3 * HID) + j] = (a0 + a1) + (a2 + a3);
        }
    } else {
        int f = bid - 60;
        if (f == 0 && j < T) g_sumexp[j] = 0.0f;
        __shared__ int toks[FACT];
        if (j < FACT) toks[j] = ctx[f * FACT + j];
        __syncthreads();
        if (j < EMB) {
            float ee = (float)j * (1.0f / 99.0f);
            float acc = 0.0f;
#pragma unroll
            for (int p = 0; p < FACT; p++) {
                float s = (float)p * (1.0f / 19.0f);
                float l = 1.0f - s - ee * (1.0f - 2.0f * s);
                acc += emb_ctx[(long)toks[p] * EMB + j] * l;
            }
            g_facts[f * EMB + j] = acc;
        }
    }
}

// ---------------- K2: h0 ----------------
__global__ void k_h0(const float* __restrict__ w1, const float* __restrict__ b1) {
    int j = blockIdx.x;
    int tid = threadIdx.x;
    const float* wr = w1 + (long)j * (CTX * HID);
    float acc = 0.0f;
    for (int k = tid; k < CTX * HID; k += 256)
        acc += g_facts[k] * wr[k];
    for (int off = 16; off; off >>= 1)
        acc += __shfl_down_sync(0xffffffffu, acc, off);
    __shared__ float s[8];
    if ((tid & 31) == 0) s[tid >> 5] = acc;
    __syncthreads();
    if (tid == 0) {
        float tot = 0.0f;
#pragma unroll
        for (int w = 0; w < 8; w++) tot += s[w];
        g_h0[j] = tot + b1[j];
    }
}

// ---------------- K3: GRU recurrence (block 0) + L2 prefetch (blocks 1..147) ----------------
__global__ void __launch_bounds__(600, 1) k_rnn(const float* __restrict__ w_hh,
                                                const float* __restrict__ b_hh,
                                                const float* __restrict__ w_out,
                                                const float* __restrict__ b_out) {
    if (blockIdx.x != 0) {
        int pid = (blockIdx.x - 1) * 600 + threadIdx.x;
        const float4* w4 = (const float4*)w_out;
        float ax = 0.0f, ay = 0.0f, az = 0.0f, aw = 0.0f;
        for (int i = pid; i < (VOCAB * HID) / 4; i += 88200) {
            float4 v = __ldg(&w4[i]);
            ax += v.x; ay += v.y; az += v.z; aw += v.w;
        }
        const float4* b4 = (const float4*)b_out;
        for (int i = pid; i < VOCAB / 4; i += 88200) {
            float4 v = __ldg(&b4[i]);
            ax += v.x; ay += v.y; az += v.z; aw += v.w;
        }
        float s = (ax + ay) + (az + aw);
        if (s == 1.23456789e30f) g_facts[0] = s;   // defeats DCE, never true
        return;
    }

    extern __shared__ __align__(16) float dyn[];
    float* sgi = dyn;            // 18000
    float* h   = dyn + 18000;    // 100
    float* ps  = h + 100;        // 600

    int tid = threadIdx.x;
    int out = tid % 300;
    int half = tid / 300;

    u64 w2[25];
    {
        const u64* wr = (const u64*)(w_hh + (long)out * HID + half * 50);
#pragma unroll
        for (int k = 0; k < 25; k++) w2[k] = wr[k];
    }
    float bhr = 0.0f, bhz = 0.0f, bhn = 0.0f;
    if (tid < HID) {
        bhr = b_hh[tid];
        bhz = b_hh[HID + tid];
        bhn = b_hh[2 * HID + tid];
    }

    for (int i = tid; i < T * 3 * HID; i += 600) sgi[i] = g_gi[i];
    if (tid < HID) h[tid] = g_h0[tid];
    __syncthreads();

    for (int t = 0; t < T; t++) {
        {
            const u64* h2 = (const u64*)(h + half * 50);
            u64 a0 = 0ull, a1 = 0ull;
#pragma unroll
            for (int k = 0; k < 12; k++) {
                ffma2(a0, w2[2 * k], h2[2 * k]);
                ffma2(a1, w2[2 * k + 1], h2[2 * k + 1]);
            }
            ffma2(a0, w2[24], h2[24]);
            ps[tid] = (f2_lo(a0) + f2_hi(a0)) + (f2_lo(a1) + f2_hi(a1));
        }
        __syncthreads();

        if (tid < HID) {
            float ghr = ps[tid]       + ps[tid + 300] + bhr;
            float ghz = ps[tid + 100] + ps[tid + 400] + bhz;
            float ghn = ps[tid + 200] + ps[tid + 500] + bhn;
            const float* gi = sgi + t * 300;
            float r = sigmoidf_(gi[tid] + ghr);
            float z = sigmoidf_(gi[HID + tid] + ghz);
            float a = gi[2 * HID + tid] + r * ghn;
            float ex = __expf(2.0f * a);
            float n = 1.0f - __fdividef(2.0f, ex + 1.0f);
            float hn = (1.0f - z) * n + z * h[tid];
            h[tid] = hn;
            g_H[t * HID + tid] = hn;
        }
        __syncthreads();
    }
}

// ---------------- K4: persistent tf32-mma logits, cp.async double buffer ----------------
// 148 blocks x 512 thr. Tile = 128 vocab rows. 16 warps = 2 m-groups (m32) x 8 n-groups (n16).
// smem floats: sA 64*108 | sB0 128*108 | sB1 128*108 | bias0 128 | bias1 128 | sSum 64*8
#define SA_F   (64 * 108)
#define SB_F   (128 * 108)
#define LOG_SMEM_FLOATS (SA_F + 2 * SB_F + 2 * 128 + 64 * 8)

__global__ void __launch_bounds__(512, 1) k_logits_pers(const float* __restrict__ w_out,
                                                        const float* __restrict__ b_out) {
    extern __shared__ __align__(16) float ldyn[];
    float* sA = ldyn;
    float* sB0 = sA + SA_F;
    float* sB1 = sB0 + SB_F;
    float* sBias0 = sB1 + SB_F;
    float* sBias1 = sBias0 + 128;
    float* sSum = sBias1 + 128;
    float* sBb[2] = { sB0, sB1 };
    float* sBi[2] = { sBias0, sBias1 };

    int tid = threadIdx.x;

    // ---- zero both B buffers (covers pad cols + uninitialized smem) ----
    for (int i = tid; i < 2 * SB_F; i += 512) sB0[i] = 0.0f;
    // ---- stage A once (g_H -> tf32, zero-padded 64x108) ----
    for (int i = tid; i < SA_F; i += 512) {
        int m = i / 108, k = i - m * 108;
        float v = (m < T && k < HID) ? g_H[m * HID + k] : 0.0f;
        sA[i] = __uint_as_float(to_tf32(v));
    }
    __syncthreads();

    // staging helper (cp.async, row-guarded)
    auto stage = [&](int tile, int buf) {
        int N0 = tile * 128;
        u32 bdst = s2u(sBb[buf]);
#pragma unroll 1
        for (int i = tid; i < 128 * 25; i += 512) {
            int n = i / 25;
            int k4 = i - n * 25;
            if (N0 + n < VOCAB)
                cp_async16(bdst + (u32)(n * 108 + k4 * 4) * 4u,
                           w_out + (size_t)(N0 + n) * HID + k4 * 4);
        }
        if (tid < 32) {
            int n4 = tid * 4;
            if (N0 + n4 + 3 < VOCAB)
                cp_async16(s2u(sBi[buf] + n4), b_out + N0 + n4);
        }
    };

    int tile0 = blockIdx.x;
    if (tile0 < NTILES) { stage(tile0, 0); }
    cp_commit();

    int lane = tid & 31;
    int warp = tid >> 5;
    int mg = warp >> 3;        // 0..1  (m32 group)
    int ng = warp & 7;         // 0..7  (n16 group)
    int grp = lane >> 2;       // 0..7
    int qi = lane & 3;         // 0..3

    // ldmatrix lane addresses for the two m16-frags of this warp's m32 slice
    u32 a_addr[2];
#pragma unroll
    for (int mi = 0; mi < 2; mi++) {
        int row = mg * 32 + mi * 16 + (lane & 15);
        int col = 4 * (lane >> 4);
        a_addr[mi] = s2u(sA + row * 108 + col);
    }

    float rowsum[4] = {0.f, 0.f, 0.f, 0.f};
    int cur = 0;

#pragma unroll 1
    for (int tile = tile0; tile < NTILES; tile += PGRID) {
        int nxt = tile + PGRID;
        if (nxt < NTILES) stage(nxt, cur ^ 1);
        cp_commit();
        cp_wait1();                 // current tile's group done
        __syncthreads();

        int N0 = tile * 128;
        // fix OOB bias slots (only last tile matters)
        if (tid < 128 && N0 + tid >= VOCAB) sBi[cur][tid] = -1e30f;
        __syncthreads();

        const float* sB = sBb[cur];
        const float* sBias = sBi[cur];

        float c[2][2][4];
#pragma unroll
        for (int mi = 0; mi < 2; mi++)
#pragma unroll
            for (int nf = 0; nf < 2; nf++)
#pragma unroll
                for (int r = 0; r < 4; r++) c[mi][nf][r] = 0.0f;

        const float* bbase = sB + (ng * 16 + grp) * 108 + qi;
#pragma unroll
        for (int kt = 0; kt < 13; kt++) {
            unsigned a[2][4];
            ldsm_x4(a[0], a_addr[0] + kt * 32);
            ldsm_x4(a[1], a_addr[1] + kt * 32);
            unsigned b[2][2];
            const float* bp = bbase + kt * 8;
            b[0][0] = __float_as_uint(bp[0]);
            b[0][1] = __float_as_uint(bp[4]);
            b[1][0] = __float_as_uint(bp[8 * 108]);
            b[1][1] = __float_as_uint(bp[8 * 108 + 4]);
#pragma unroll
            for (int mi = 0; mi < 2; mi++)
#pragma unroll
                for (int nf = 0; nf < 2; nf++)
                    mma_tf32(c[mi][nf], a[mi], b[nf]);
        }

        // epilogue: exp + accumulate into persistent regs
#pragma unroll
        for (int nf = 0; nf < 2; nf++) {
            int n0 = ng * 16 + nf * 8 + 2 * qi;
            float bias0 = sBias[n0];
            float bias1 = sBias[n0 + 1];
#pragma unroll
            for (int mi = 0; mi < 2; mi++) {
                rowsum[mi * 2]     += __expf(c[mi][nf][0] + bias0) + __expf(c[mi][nf][1] + bias1);
                rowsum[mi * 2 + 1] += __expf(c[mi][nf][2] + bias0) + __expf(c[mi][nf][3] + bias1);
            }
        }
        __syncthreads();        // compute done before next cp.async overwrites cur^1's partner
        cur ^= 1;
    }

    // cross-lane reduce over qi (lanes of a group hold same rows, different cols)
#pragma unroll
    for (int j = 0; j < 4; j++) {
        rowsum[j] += __shfl_xor_sync(0xffffffffu, rowsum[j], 1);
        rowsum[j] += __shfl_xor_sync(0xffffffffu, rowsum[j], 2);
    }
    if (qi == 0) {
#pragma unroll
        for (int j = 0; j < 4; j++) {
            int row = mg * 32 + (j >> 1) * 16 + (j & 1) * 8 + grp;
            sSum[row * 8 + ng] = rowsum[j];
        }
    }
    __syncthreads();
    if (tid < 64) {
        float s = 0.0f;
#pragma unroll
        for (int w = 0; w < 8; w++) s += sSum[tid * 8 + w];
        if (tid < T) atomicAdd(&g_sumexp[tid], s);
    }
}

// ---------------- K5: token logits + final loss ----------------
__global__ void __launch_bounds__(512) k_final(const float* __restrict__ w_out,
                                               const float* __restrict__ b_out,
                                               const int* __restrict__ desc,
                                               float* __restrict__ out) {
    __shared__ float tl[T];
    __shared__ float red[16];
    int tid = threadIdx.x;
    int wid = tid >> 5;
    int lane = tid & 31;

#pragma unroll
    for (int i = 0; i < 4; i++) {
        int t = wid * 4 + i;
        if (t < T) {
            int tok = desc[t];
            const float* wr = w_out + (size_t)tok * HID;
            const float* hr = g_H + t * HID;
            float acc = wr[lane] * hr[lane]
                      + wr[lane + 32] * hr[lane + 32]
                      + wr[lane + 64] * hr[lane + 64];
            if (lane < 4) acc += wr[lane + 96] * hr[lane + 96];
#pragma unroll
            for (int off = 16; off; off >>= 1)
                acc += __shfl_down_sync(0xffffffffu, acc, off);
            if (lane == 0) tl[t] = acc + b_out[tok];
        }
    }
    __syncthreads();

    float v = 0.0f;
    if (tid < T) v = logf(g_sumexp[tid]) - tl[tid];
#pragma unroll
    for (int off = 16; off; off >>= 1)
        v += __shfl_down_sync(0xffffffffu, v, off);
    if (lane == 0) red[wid] = v;
    __syncthreads();
    if (tid == 0) out[0] = red[0] + red[1];
}

// ---------------- launch ----------------
extern "C" void kernel_launch(void* const* d_in, const int* in_sizes, int n_in,
                              void* d_out, int out_size) {
    const int*   context  = (const int*)d_in[0];
    const int*   desc     = (const int*)d_in[2];
    const float* emb_ctx  = (const float*)d_in[3];
    const float* emb_dec  = (const float*)d_in[4];
    const float* w1       = (const float*)d_in[5];
    const float* b1       = (const float*)d_in[6];
    const float* w_ih     = (const float*)d_in[7];
    const float* w_hh     = (const float*)d_in[8];
    const float* b_ih     = (const float*)d_in[9];
    const float* b_hh     = (const float*)d_in[10];
    const float* w_out    = (const float*)d_in[11];
    const float* b_out    = (const float*)d_in[12];
    float* out = (float*)d_out;

    const int rnn_smem = (T * 3 * HID + HID + 600) * (int)sizeof(float);   // 74800 B
    const int log_smem = LOG_SMEM_FLOATS * (int)sizeof(float);             // 141312 B
    cudaFuncSetAttribute(k_rnn, cudaFuncAttributeMaxDynamicSharedMemorySize, rnn_smem);
    cudaFuncSetAttribute(k_logits_pers, cudaFuncAttributeMaxDynamicSharedMemorySize, log_smem);

    k_pre<<<120, 320>>>(context, emb_ctx, desc, emb_dec, w_ih, b_ih);
    k_h0<<<HID, 256>>>(w1, b1);
    k_rnn<<<148, 600, rnn_smem>>>(w_hh, b_hh, w_out, b_out);
    k_logits_pers<<<PGRID, 512, log_smem>>>(w_out, b_out);
    k_final<<<1, 512>>>(w_out, b_out, desc, out);
}

// round 10
// speedup vs baseline: 1.5982x; 1.0497x over previous
#include <cuda_runtime.h>
#include <math.h>

#define VOCAB 100000
#define EMB   100
#define HID   100
#define CTX   60
#define FACT  20
#define T     60
#define NTILES 782        // ceil(100000 / 128)
#define NWORK  147        // logits worker blocks

typedef unsigned long long u64;
typedef unsigned int u32;

// ---------------- scratch ----------------
__device__ float g_facts[CTX * EMB];
__device__ float g_h0[HID];
__device__ float g_gi[T * 3 * HID];
__device__ float g_H[T * HID];
__device__ float g_sumexp[T];
__device__ int   g_flag;
__device__ float g_sink;

__device__ __forceinline__ float sigmoidf_(float x) {
    return 1.0f / (1.0f + __expf(-x));
}
__device__ __forceinline__ void ffma2(u64 &d, u64 a, u64 b) {
    asm("fma.rn.f32x2 %0, %1, %2, %0;" : "+l"(d) : "l"(a), "l"(b));
}
__device__ __forceinline__ float f2_lo(u64 v) { return __int_as_float((int)(v & 0xffffffffull)); }
__device__ __forceinline__ float f2_hi(u64 v) { return __int_as_float((int)(v >> 32)); }
__device__ __forceinline__ unsigned to_tf32(float f) {
    unsigned r;
    asm("cvt.rna.tf32.f32 %0, %1;" : "=r"(r) : "f"(f));
    return r;
}
__device__ __forceinline__ void mma_tf32(float* c, const unsigned* a, const unsigned* b) {
    asm volatile(
        "mma.sync.aligned.m16n8k8.row.col.f32.tf32.tf32.f32 "
        "{%0,%1,%2,%3}, {%4,%5,%6,%7}, {%8,%9}, {%0,%1,%2,%3};"
        : "+f"(c[0]), "+f"(c[1]), "+f"(c[2]), "+f"(c[3])
        : "r"(a[0]), "r"(a[1]), "r"(a[2]), "r"(a[3]), "r"(b[0]), "r"(b[1]));
}
__device__ __forceinline__ u32 s2u(const void* p) {
    return (u32)__cvta_generic_to_shared(p);
}
__device__ __forceinline__ void cp_async16(u32 dst, const void* src) {
    asm volatile("cp.async.cg.shared.global [%0], [%1], 16;" :: "r"(dst), "l"(src));
}
__device__ __forceinline__ void cp_commit() {
    asm volatile("cp.async.commit_group;");
}
__device__ __forceinline__ void cp_wait1() {
    asm volatile("cp.async.wait_group 1;");
}
__device__ __forceinline__ void ldsm_x4(unsigned* r, u32 addr) {
    asm volatile("ldmatrix.sync.aligned.m8n8.x4.shared.b16 {%0,%1,%2,%3}, [%4];"
                 : "=r"(r[0]), "=r"(r[1]), "=r"(r[2]), "=r"(r[3]) : "r"(addr));
}

// ---------------- K_pre: gi (blocks 0..59) + facts (blocks 60..119) ----------------
__global__ void __launch_bounds__(320) k_pre(const int* __restrict__ ctx,
                                             const float* __restrict__ emb_ctx,
                                             const int* __restrict__ desc,
                                             const float* __restrict__ emb_dec,
                                             const float* __restrict__ w_ih,
                                             const float* __restrict__ b_ih) {
    int bid = blockIdx.x;
    int j = threadIdx.x;
    if (bid < 60) {
        int t = bid;
        __shared__ __align__(16) float x[EMB];
        __shared__ int tok;
        if (j == 0) tok = (t == 0) ? 1 : desc[t - 1];
        __syncthreads();
        if (j < EMB) x[j] = emb_dec[(long)tok * EMB + j];
        __syncthreads();
        if (j < 3 * HID) {
            const float4* w4 = (const float4*)(w_ih + (long)j * EMB);
            const float4* x4 = (const float4*)x;
            float a0 = b_ih[j], a1 = 0.0f, a2 = 0.0f, a3 = 0.0f;
#pragma unroll
            for (int k = 0; k < 25; k++) {
                float4 w = w4[k];
                float4 h = x4[k];
                a0 += w.x * h.x; a1 += w.y * h.y; a2 += w.z * h.z; a3 += w.w * h.w;
            }
            g_gi[t * (3 * HID) + j] = (a0 + a1) + (a2 + a3);
        }
    } else {
        int f = bid - 60;
        if (f == 0 && j < T) g_sumexp[j] = 0.0f;
        if (f == 0 && j == 0) g_flag = 0;
        __shared__ int toks[FACT];
        if (j < FACT) toks[j] = ctx[f * FACT + j];
        __syncthreads();
        if (j < EMB) {
            float ee = (float)j * (1.0f / 99.0f);
            float acc = 0.0f;
#pragma unroll
            for (int p = 0; p < FACT; p++) {
                float s = (float)p * (1.0f / 19.0f);
                float l = 1.0f - s - ee * (1.0f - 2.0f * s);
                acc += emb_ctx[(long)toks[p] * EMB + j] * l;
            }
            g_facts[f * EMB + j] = acc;
        }
    }
}

// ---------------- K2: h0 ----------------
__global__ void k_h0(const float* __restrict__ w1, const float* __restrict__ b1) {
    int j = blockIdx.x;
    int tid = threadIdx.x;
    const float* wr = w1 + (long)j * (CTX * HID);
    float acc = 0.0f;
    for (int k = tid; k < CTX * HID; k += 256)
        acc += g_facts[k] * wr[k];
    for (int off = 16; off; off >>= 1)
        acc += __shfl_down_sync(0xffffffffu, acc, off);
    __shared__ float s[8];
    if ((tid & 31) == 0) s[tid >> 5] = acc;
    __syncthreads();
    if (tid == 0) {
        float tot = 0.0f;
#pragma unroll
        for (int w = 0; w < 8; w++) tot += s[w];
        g_h0[j] = tot + b1[j];
    }
}

// ---------------- K_main: fused recurrence (block 0) + logits GEMM (blocks 1..147) ----------------
// smem floats: sA 64*108 | sB0 128*108 | sB1 128*108 | bias0 128 | bias1 128 | sSum 64*8
#define SA_F   (64 * 108)
#define SB_F   (128 * 108)
#define MAIN_SMEM_FLOATS (SA_F + 2 * SB_F + 2 * 128 + 64 * 8)

__global__ void __launch_bounds__(600, 1) k_main(const float* __restrict__ w_hh,
                                                 const float* __restrict__ b_hh,
                                                 const float* __restrict__ w_out,
                                                 const float* __restrict__ b_out) {
    extern __shared__ __align__(16) float dyn[];
    int tid = threadIdx.x;

    if (blockIdx.x == 0) {
        // ================= GRU recurrence =================
        float* sgi = dyn;            // 18000
        float* h   = dyn + 18000;    // 100
        float* ps  = h + 100;        // 600

        int out = tid % 300;
        int half = tid / 300;

        u64 w2[25];
        {
            const u64* wr = (const u64*)(w_hh + (long)out * HID + half * 50);
#pragma unroll
            for (int k = 0; k < 25; k++) w2[k] = wr[k];
        }
        float bhr = 0.0f, bhz = 0.0f, bhn = 0.0f;
        if (tid < HID) {
            bhr = b_hh[tid];
            bhz = b_hh[HID + tid];
            bhn = b_hh[2 * HID + tid];
        }

        for (int i = tid; i < T * 3 * HID; i += 600) sgi[i] = g_gi[i];
        if (tid < HID) h[tid] = g_h0[tid];
        __syncthreads();

        for (int t = 0; t < T; t++) {
            {
                const u64* h2 = (const u64*)(h + half * 50);
                u64 a0 = 0ull, a1 = 0ull;
#pragma unroll
                for (int k = 0; k < 12; k++) {
                    ffma2(a0, w2[2 * k], h2[2 * k]);
                    ffma2(a1, w2[2 * k + 1], h2[2 * k + 1]);
                }
                ffma2(a0, w2[24], h2[24]);
                ps[tid] = (f2_lo(a0) + f2_hi(a0)) + (f2_lo(a1) + f2_hi(a1));
            }
            __syncthreads();

            if (tid < HID) {
                float ghr = ps[tid]       + ps[tid + 300] + bhr;
                float ghz = ps[tid + 100] + ps[tid + 400] + bhz;
                float ghn = ps[tid + 200] + ps[tid + 500] + bhn;
                const float* gi = sgi + t * 300;
                float r = sigmoidf_(gi[tid] + ghr);
                float z = sigmoidf_(gi[HID + tid] + ghz);
                float a = gi[2 * HID + tid] + r * ghn;
                float ex = __expf(2.0f * a);
                float n = 1.0f - __fdividef(2.0f, ex + 1.0f);
                float hn = (1.0f - z) * n + z * h[tid];
                h[tid] = hn;
                g_H[t * HID + tid] = hn;
            }
            if (t == 31) {
                __threadfence();        // all threads: order g_H rows 0..31 to GPU scope
                __syncthreads();
                if (tid == 0) *(volatile int*)&g_flag = 1;
            } else {
                __syncthreads();
            }
        }
        __threadfence();
        __syncthreads();
        if (tid == 0) *(volatile int*)&g_flag = 2;
        return;
    }

    // ================= logits workers =================
    float* sA = dyn;
    float* sB0 = sA + SA_F;
    float* sB1 = sB0 + SB_F;
    float* sBias0 = sB1 + SB_F;
    float* sBias1 = sBias0 + 128;
    float* sSum = sBias1 + 128;
    float* sBb[2] = { sB0, sB1 };
    float* sBi[2] = { sBias0, sBias1 };

    int bix = blockIdx.x - 1;   // 0..146

    // zero B buffers (pad cols stay 0 forever)
    for (int i = tid; i < 2 * SB_F; i += 600) sB0[i] = 0.0f;

    // ---- warm L2 with this block's w_out tiles while the recurrence runs ----
    {
        float acc = 0.0f;
        const float4* w4 = (const float4*)w_out;
        for (int tile = bix; tile < NTILES; tile += NWORK) {
            int N0 = tile * 128;
            for (int i = tid; i < 128 * 25; i += 600) {
                int n = i / 25;
                if (N0 + n < VOCAB) {
                    float4 v = __ldg(&w4[(size_t)(N0 + n) * 25 + (i - n * 25)]);
                    acc += v.x + v.y + v.z + v.w;
                }
            }
        }
        if (acc == 1.23456789e30f) g_sink = acc;   // never true; defeats DCE
    }

    int lane = tid & 31;
    int warp = tid >> 5;
    int mg = warp >> 3;        // 0..1  (m16 group within the pass's 32 rows)
    int ng = warp & 7;         // 0..7  (n16 group)
    int grp = lane >> 2;       // 0..7
    int qi = lane & 3;         // 0..3

    // staging helper (cp.async, row-guarded)
    auto stage = [&](int tile, int buf) {
        int N0 = tile * 128;
        u32 bdst = s2u(sBb[buf]);
#pragma unroll 1
        for (int i = tid; i < 128 * 25; i += 600) {
            int n = i / 25;
            int k4 = i - n * 25;
            if (N0 + n < VOCAB)
                cp_async16(bdst + (u32)(n * 108 + k4 * 4) * 4u,
                           w_out + (size_t)(N0 + n) * HID + k4 * 4);
        }
        if (tid < 32) {
            int n4 = tid * 4;
            if (N0 + n4 + 3 < VOCAB)
                cp_async16(s2u(sBi[buf] + n4), b_out + N0 + n4);
        }
    };

    float rowsum[4] = {0.f, 0.f, 0.f, 0.f};    // [pass*2 + (0: row grp, 1: row grp+8)]

#pragma unroll 1
    for (int pass = 0; pass < 2; pass++) {
        // wait for H rows [pass*32, pass*32+32)
        if (tid == 0) {
            while (*(volatile int*)&g_flag < pass + 1) __nanosleep(64);
        }
        __syncthreads();
        __threadfence();

        // stage A rows for this pass (tf32, zero-padded)
        for (int i = tid; i < 32 * 108; i += 600) {
            int m = i / 108, k = i - m * 108;
            int row = pass * 32 + m;
            float v = (row < T && k < HID) ? g_H[row * HID + k] : 0.0f;
            sA[row * 108 + k] = __uint_as_float(to_tf32(v));
        }
        __syncthreads();

        u32 a_addr = s2u(sA + (pass * 32 + mg * 16 + (lane & 15)) * 108 + 4 * (lane >> 4));

        int cur = 0;
        stage(bix, 0);
        cp_commit();

#pragma unroll 1
        for (int tile = bix; tile < NTILES; tile += NWORK) {
            int nxt = tile + NWORK;
            if (nxt < NTILES) stage(nxt, cur ^ 1);
            cp_commit();
            cp_wait1();
            __syncthreads();

            int N0 = tile * 128;
            if (N0 + 128 > VOCAB) {                 // boundary tile only
                if (tid < 128 && N0 + tid >= VOCAB) sBi[cur][tid] = -1e30f;
                __syncthreads();
            }

            if (tid < 512) {
                const float* sB = sBb[cur];
                const float* sBias = sBi[cur];

                float c[2][4];
#pragma unroll
                for (int nf = 0; nf < 2; nf++)
#pragma unroll
                    for (int r = 0; r < 4; r++) c[nf][r] = 0.0f;

                const float* bbase = sB + (ng * 16 + grp) * 108 + qi;
#pragma unroll
                for (int kt = 0; kt < 13; kt++) {
                    unsigned a[4];
                    ldsm_x4(a, a_addr + kt * 32);
                    unsigned b[2][2];
                    const float* bp = bbase + kt * 8;
                    b[0][0] = __float_as_uint(bp[0]);
                    b[0][1] = __float_as_uint(bp[4]);
                    b[1][0] = __float_as_uint(bp[8 * 108]);
                    b[1][1] = __float_as_uint(bp[8 * 108 + 4]);
                    mma_tf32(c[0], a, b[0]);
                    mma_tf32(c[1], a, b[1]);
                }

#pragma unroll
                for (int nf = 0; nf < 2; nf++) {
                    int n0 = ng * 16 + nf * 8 + 2 * qi;
                    float bias0 = sBias[n0];
                    float bias1 = sBias[n0 + 1];
                    rowsum[pass * 2]     += __expf(c[nf][0] + bias0) + __expf(c[nf][1] + bias1);
                    rowsum[pass * 2 + 1] += __expf(c[nf][2] + bias0) + __expf(c[nf][3] + bias1);
                }
            }
            __syncthreads();
            cur ^= 1;
        }
    }

    // cross-lane reduce over qi and write out
#pragma unroll
    for (int j = 0; j < 4; j++) {
        rowsum[j] += __shfl_xor_sync(0xffffffffu, rowsum[j], 1);
        rowsum[j] += __shfl_xor_sync(0xffffffffu, rowsum[j], 2);
    }
    if (tid < 512 && qi == 0) {
#pragma unroll
        for (int j = 0; j < 4; j++) {
            int row = (j >> 1) * 32 + mg * 16 + (j & 1) * 8 + grp;
            sSum[row * 8 + ng] = rowsum[j];
        }
    }
    __syncthreads();
    if (tid < 64) {
        float s = 0.0f;
#pragma unroll
        for (int w = 0; w < 8; w++) s += sSum[tid * 8 + w];
        if (tid < T) atomicAdd(&g_sumexp[tid], s);
    }
}

// ---------------- K5: token logits + final loss ----------------
__global__ void __launch_bounds__(512) k_final(const float* __restrict__ w_out,
                                               const float* __restrict__ b_out,
                                               const int* __restrict__ desc,
                                               float* __restrict__ out) {
    __shared__ float tl[T];
    __shared__ float red[16];
    int tid = threadIdx.x;
    int wid = tid >> 5;
    int lane = tid & 31;

#pragma unroll
    for (int i = 0; i < 4; i++) {
        int t = wid * 4 + i;
        if (t < T) {
            int tok = desc[t];
            const float* wr = w_out + (size_t)tok * HID;
            const float* hr = g_H + t * HID;
            float acc = wr[lane] * hr[lane]
                      + wr[lane + 32] * hr[lane + 32]
                      + wr[lane + 64] * hr[lane + 64];
            if (lane < 4) acc += wr[lane + 96] * hr[lane + 96];
#pragma unroll
            for (int off = 16; off; off >>= 1)
                acc += __shfl_down_sync(0xffffffffu, acc, off);
            if (lane == 0) tl[t] = acc + b_out[tok];
        }
    }
    __syncthreads();

    float v = 0.0f;
    if (tid < T) v = logf(g_sumexp[tid]) - tl[tid];
#pragma unroll
    for (int off = 16; off; off >>= 1)
        v += __shfl_down_sync(0xffffffffu, v, off);
    if (lane == 0) red[wid] = v;
    __syncthreads();
    if (tid == 0) out[0] = red[0] + red[1];
}

// ---------------- launch ----------------
extern "C" void kernel_launch(void* const* d_in, const int* in_sizes, int n_in,
                              void* d_out, int out_size) {
    const int*   context  = (const int*)d_in[0];
    const int*   desc     = (const int*)d_in[2];
    const float* emb_ctx  = (const float*)d_in[3];
    const float* emb_dec  = (const float*)d_in[4];
    const float* w1       = (const float*)d_in[5];
    const float* b1       = (const float*)d_in[6];
    const float* w_ih     = (const float*)d_in[7];
    const float* w_hh     = (const float*)d_in[8];
    const float* b_ih     = (const float*)d_in[9];
    const float* b_hh     = (const float*)d_in[10];
    const float* w_out    = (const float*)d_in[11];
    const float* b_out    = (const float*)d_in[12];
    float* out = (float*)d_out;

    const int main_smem = MAIN_SMEM_FLOATS * (int)sizeof(float);   // 141312 B
    cudaFuncSetAttribute(k_main, cudaFuncAttributeMaxDynamicSharedMemorySize, main_smem);

    k_pre<<<120, 320>>>(context, emb_ctx, desc, emb_dec, w_ih, b_ih);
    k_h0<<<HID, 256>>>(w1, b1);
    k_main<<<148, 600, main_smem>>>(w_hh, b_hh, w_out, b_out);
    k_final<<<1, 512>>>(w_out, b_out, desc, out);
}

// round 11
// speedup vs baseline: 1.6941x; 1.0600x over previous
#include <cuda_runtime.h>
#include <math.h>

#define VOCAB 100000
#define EMB   100
#define HID   100
#define CTX   60
#define FACT  20
#define T     60
#define NTILES 782        // ceil(100000 / 128)
#define NWORK  147        // logits worker blocks

typedef unsigned long long u64;
typedef unsigned int u32;

// ---------------- scratch ----------------
__device__ float g_facts[CTX * EMB];
__device__ float g_h0[HID];
__device__ float g_gi[T * 3 * HID];
__device__ float g_H[T * HID];
__device__ float g_sumexp[T];
__device__ int   g_flag;
__device__ int   g_cnt0;      // h0 rows done
__device__ int   g_cnt1;      // worker blocks done
__device__ float g_sink;

__device__ __forceinline__ float sigmoidf_(float x) {
    return 1.0f / (1.0f + __expf(-x));
}
__device__ __forceinline__ void ffma2(u64 &d, u64 a, u64 b) {
    asm("fma.rn.f32x2 %0, %1, %2, %0;" : "+l"(d) : "l"(a), "l"(b));
}
__device__ __forceinline__ float f2_lo(u64 v) { return __int_as_float((int)(v & 0xffffffffull)); }
__device__ __forceinline__ float f2_hi(u64 v) { return __int_as_float((int)(v >> 32)); }
__device__ __forceinline__ unsigned to_tf32(float f) {
    unsigned r;
    asm("cvt.rna.tf32.f32 %0, %1;" : "=r"(r) : "f"(f));
    return r;
}
__device__ __forceinline__ void mma_tf32(float* c, const unsigned* a, const unsigned* b) {
    asm volatile(
        "mma.sync.aligned.m16n8k8.row.col.f32.tf32.tf32.f32 "
        "{%0,%1,%2,%3}, {%4,%5,%6,%7}, {%8,%9}, {%0,%1,%2,%3};"
        : "+f"(c[0]), "+f"(c[1]), "+f"(c[2]), "+f"(c[3])
        : "r"(a[0]), "r"(a[1]), "r"(a[2]), "r"(a[3]), "r"(b[0]), "r"(b[1]));
}
__device__ __forceinline__ u32 s2u(const void* p) {
    return (u32)__cvta_generic_to_shared(p);
}
__device__ __forceinline__ void cp_async16(u32 dst, const void* src) {
    asm volatile("cp.async.cg.shared.global [%0], [%1], 16;" :: "r"(dst), "l"(src));
}
__device__ __forceinline__ void cp_commit() {
    asm volatile("cp.async.commit_group;");
}
__device__ __forceinline__ void cp_wait1() {
    asm volatile("cp.async.wait_group 1;");
}
__device__ __forceinline__ void ldsm_x4(unsigned* r, u32 addr) {
    asm volatile("ldmatrix.sync.aligned.m8n8.x4.shared.b16 {%0,%1,%2,%3}, [%4];"
                 : "=r"(r[0]), "=r"(r[1]), "=r"(r[2]), "=r"(r[3]) : "r"(addr));
}

// ---------------- K_pre: gi (blocks 0..59) + facts (blocks 60..119) + resets ----------------
__global__ void __launch_bounds__(320) k_pre(const int* __restrict__ ctx,
                                             const float* __restrict__ emb_ctx,
                                             const int* __restrict__ desc,
                                             const float* __restrict__ emb_dec,
                                             const float* __restrict__ w_ih,
                                             const float* __restrict__ b_ih) {
    int bid = blockIdx.x;
    int j = threadIdx.x;
    if (bid < 60) {
        int t = bid;
        __shared__ __align__(16) float x[EMB];
        __shared__ int tok;
        if (j == 0) tok = (t == 0) ? 1 : desc[t - 1];
        __syncthreads();
        if (j < EMB) x[j] = emb_dec[(long)tok * EMB + j];
        __syncthreads();
        if (j < 3 * HID) {
            const float4* w4 = (const float4*)(w_ih + (long)j * EMB);
            const float4* x4 = (const float4*)x;
            float a0 = b_ih[j], a1 = 0.0f, a2 = 0.0f, a3 = 0.0f;
#pragma unroll
            for (int k = 0; k < 25; k++) {
                float4 w = w4[k];
                float4 h = x4[k];
                a0 += w.x * h.x; a1 += w.y * h.y; a2 += w.z * h.z; a3 += w.w * h.w;
            }
            g_gi[t * (3 * HID) + j] = (a0 + a1) + (a2 + a3);
        }
    } else {
        int f = bid - 60;
        if (f == 0 && j < T) g_sumexp[j] = 0.0f;
        if (f == 0 && j == 0) { g_flag = 0; g_cnt0 = 0; g_cnt1 = 0; }
        __shared__ int toks[FACT];
        if (j < FACT) toks[j] = ctx[f * FACT + j];
        __syncthreads();
        if (j < EMB) {
            float ee = (float)j * (1.0f / 99.0f);
            float acc = 0.0f;
#pragma unroll
            for (int p = 0; p < FACT; p++) {
                float s = (float)p * (1.0f / 19.0f);
                float l = 1.0f - s - ee * (1.0f - 2.0f * s);
                acc += emb_ctx[(long)toks[p] * EMB + j] * l;
            }
            g_facts[f * EMB + j] = acc;
        }
    }
}

// ---------------- K_main: everything else, one launch ----------------
// smem floats: sA 64*108 | sB0 128*108 | sB1 128*108 | bias0 128 | bias1 128 | sSum 64*8
#define SA_F   (64 * 108)
#define SB_F   (128 * 108)
#define MAIN_SMEM_FLOATS (SA_F + 2 * SB_F + 2 * 128 + 64 * 8)

__global__ void __launch_bounds__(600, 1) k_main(const float* __restrict__ w_hh,
                                                 const float* __restrict__ b_hh,
                                                 const float* __restrict__ w_out,
                                                 const float* __restrict__ b_out,
                                                 const float* __restrict__ w1,
                                                 const float* __restrict__ b1,
                                                 const int* __restrict__ desc,
                                                 float* __restrict__ out) {
    extern __shared__ __align__(16) float dyn[];
    int tid = threadIdx.x;

    if (blockIdx.x == 0) {
        // ================= GRU recurrence + token logits + final loss =================
        float* sgi = dyn;            // 18000
        float* h   = dyn + 18000;    // 100
        float* ps  = h + 100;        // 600
        float* tl  = ps + 600;       // 60
        float* red = tl + 64;        // 2

        int outj = tid % 300;
        int half = tid / 300;

        u64 w2[25];
        {
            const u64* wr = (const u64*)(w_hh + (long)outj * HID + half * 50);
#pragma unroll
            for (int k = 0; k < 25; k++) w2[k] = wr[k];
        }
        float bhr = 0.0f, bhz = 0.0f, bhn = 0.0f;
        if (tid < HID) {
            bhr = b_hh[tid];
            bhz = b_hh[HID + tid];
            bhn = b_hh[2 * HID + tid];
        }

        for (int i = tid; i < T * 3 * HID; i += 600) sgi[i] = g_gi[i];

        // wait for workers to publish h0 (100 rows)
        if (tid == 0) {
            while (*(volatile int*)&g_cnt0 < 100) __nanosleep(32);
        }
        __syncthreads();
        __threadfence();
        if (tid < HID) h[tid] = *((volatile float*)&g_h0[tid]);
        __syncthreads();

        for (int t = 0; t < T; t++) {
            {
                const u64* h2 = (const u64*)(h + half * 50);
                u64 a0 = 0ull, a1 = 0ull;
#pragma unroll
                for (int k = 0; k < 12; k++) {
                    ffma2(a0, w2[2 * k], h2[2 * k]);
                    ffma2(a1, w2[2 * k + 1], h2[2 * k + 1]);
                }
                ffma2(a0, w2[24], h2[24]);
                ps[tid] = (f2_lo(a0) + f2_hi(a0)) + (f2_lo(a1) + f2_hi(a1));
            }
            __syncthreads();

            if (tid < HID) {
                float ghr = ps[tid]       + ps[tid + 300] + bhr;
                float ghz = ps[tid + 100] + ps[tid + 400] + bhz;
                float ghn = ps[tid + 200] + ps[tid + 500] + bhn;
                const float* gi = sgi + t * 300;
                float r = sigmoidf_(gi[tid] + ghr);
                float z = sigmoidf_(gi[HID + tid] + ghz);
                float a = gi[2 * HID + tid] + r * ghn;
                float ex = __expf(2.0f * a);
                float n = 1.0f - __fdividef(2.0f, ex + 1.0f);
                float hn = (1.0f - z) * n + z * h[tid];
                h[tid] = hn;
                g_H[t * HID + tid] = hn;
            }
            if (t == 31) {
                __threadfence();
                __syncthreads();
                if (tid == 0) *(volatile int*)&g_flag = 1;
            } else {
                __syncthreads();
            }
        }
        __threadfence();
        __syncthreads();
        if (tid == 0) *(volatile int*)&g_flag = 2;

        // ---- token logits (overlaps workers' pass B; w_out rows are L2-warm) ----
        {
            int wid = tid >> 5;
            int lane = tid & 31;
            if (wid < 15) {
#pragma unroll
                for (int i = 0; i < 4; i++) {
                    int t = wid * 4 + i;
                    int tok = desc[t];
                    const float* wr = w_out + (size_t)tok * HID;
                    const float* hr = g_H + t * HID;
                    float acc = wr[lane] * hr[lane]
                              + wr[lane + 32] * hr[lane + 32]
                              + wr[lane + 64] * hr[lane + 64];
                    if (lane < 4) acc += wr[lane + 96] * hr[lane + 96];
#pragma unroll
                    for (int off = 16; off; off >>= 1)
                        acc += __shfl_down_sync(0xffffffffu, acc, off);
                    if (lane == 0) tl[t] = acc + b_out[tok];
                }
            }
        }

        // ---- wait for all workers, then final loss ----
        if (tid == 0) {
            while (*(volatile int*)&g_cnt1 < NWORK) __nanosleep(64);
        }
        __syncthreads();
        __threadfence();
        {
            float v = 0.0f;
            if (tid < T) v = logf(((volatile float*)g_sumexp)[tid]) - tl[tid];
            if (tid < 64) {
#pragma unroll
                for (int off = 16; off; off >>= 1)
                    v += __shfl_down_sync(0xffffffffu, v, off);
                if ((tid & 31) == 0) red[tid >> 5] = v;
            }
            __syncthreads();
            if (tid == 0) out[0] = red[0] + red[1];
        }
        return;
    }

    // ================= workers: h0, L2 warm, logits GEMM =================
    float* sA = dyn;
    float* sB0 = sA + SA_F;
    float* sB1 = sB0 + SB_F;
    float* sBias0 = sB1 + SB_F;
    float* sBias1 = sBias0 + 128;
    float* sSum = sBias1 + 128;
    float* sBb[2] = { sB0, sB1 };
    float* sBi[2] = { sBias0, sBias1 };

    int bix = blockIdx.x - 1;   // 0..146
    int lane = tid & 31;
    int warp = tid >> 5;

    // zero B buffers (pad cols stay 0 forever)
    for (int i = tid; i < 2 * SB_F; i += 600) sB0[i] = 0.0f;

    // ---- h0 row (blocks 1..100) ----
    if (bix < 100) {
        float acc = 0.0f;
        if (tid < 512) {
            const float* wr = w1 + (long)bix * (CTX * HID);
            for (int k = tid; k < CTX * HID; k += 512)
                acc += g_facts[k] * wr[k];
#pragma unroll
            for (int off = 16; off; off >>= 1)
                acc += __shfl_down_sync(0xffffffffu, acc, off);
            if (lane == 0) sSum[warp] = acc;
        }
        __syncthreads();
        if (tid == 0) {
            float tot = 0.0f;
#pragma unroll
            for (int w = 0; w < 16; w++) tot += sSum[w];
            g_h0[bix] = tot + b1[bix];
            __threadfence();
            atomicAdd(&g_cnt0, 1);
        }
        __syncthreads();
    }

    // ---- warm L2 with this block's w_out tiles while the recurrence runs ----
    {
        float acc = 0.0f;
        const float4* w4 = (const float4*)w_out;
        for (int tile = bix; tile < NTILES; tile += NWORK) {
            int N0 = tile * 128;
            for (int i = tid; i < 128 * 25; i += 600) {
                int n = i / 25;
                if (N0 + n < VOCAB) {
                    float4 v = __ldg(&w4[(size_t)(N0 + n) * 25 + (i - n * 25)]);
                    acc += v.x + v.y + v.z + v.w;
                }
            }
        }
        if (acc == 1.23456789e30f) g_sink = acc;   // never true; defeats DCE
    }

    int mg = warp >> 3;        // 0..1  (m16 group within the pass's 32 rows)
    int ng = warp & 7;         // 0..7  (n16 group)
    int grp = lane >> 2;       // 0..7
    int qi = lane & 3;         // 0..3

    auto stage = [&](int tile, int buf) {
        int N0 = tile * 128;
        u32 bdst = s2u(sBb[buf]);
#pragma unroll 1
        for (int i = tid; i < 128 * 25; i += 600) {
            int n = i / 25;
            int k4 = i - n * 25;
            if (N0 + n < VOCAB)
                cp_async16(bdst + (u32)(n * 108 + k4 * 4) * 4u,
                           w_out + (size_t)(N0 + n) * HID + k4 * 4);
        }
        if (tid < 32) {
            int n4 = tid * 4;
            if (N0 + n4 + 3 < VOCAB)
                cp_async16(s2u(sBi[buf] + n4), b_out + N0 + n4);
        }
    };

    float rowsum[4] = {0.f, 0.f, 0.f, 0.f};

#pragma unroll 1
    for (int pass = 0; pass < 2; pass++) {
        if (tid == 0) {
            while (*(volatile int*)&g_flag < pass + 1) __nanosleep(64);
        }
        __syncthreads();
        __threadfence();

        for (int i = tid; i < 32 * 108; i += 600) {
            int m = i / 108, k = i - m * 108;
            int row = pass * 32 + m;
            float v = (row < T && k < HID) ? g_H[row * HID + k] : 0.0f;
            sA[row * 108 + k] = __uint_as_float(to_tf32(v));
        }
        __syncthreads();

        u32 a_addr = s2u(sA + (pass * 32 + mg * 16 + (lane & 15)) * 108 + 4 * (lane >> 4));

        int cur = 0;
        stage(bix, 0);
        cp_commit();

#pragma unroll 1
        for (int tile = bix; tile < NTILES; tile += NWORK) {
            int nxt = tile + NWORK;
            if (nxt < NTILES) stage(nxt, cur ^ 1);
            cp_commit();
            cp_wait1();
            __syncthreads();

            int N0 = tile * 128;
            if (N0 + 128 > VOCAB) {
                if (tid < 128 && N0 + tid >= VOCAB) sBi[cur][tid] = -1e30f;
                __syncthreads();
            }

            if (tid < 512) {
                const float* sB = sBb[cur];
                const float* sBias = sBi[cur];

                float c[2][4];
#pragma unroll
                for (int nf = 0; nf < 2; nf++)
#pragma unroll
                    for (int r = 0; r < 4; r++) c[nf][r] = 0.0f;

                const float* bbase = sB + (ng * 16 + grp) * 108 + qi;
#pragma unroll
                for (int kt = 0; kt < 13; kt++) {
                    unsigned a[4];
                    ldsm_x4(a, a_addr + kt * 32);
                    unsigned b[2][2];
                    const float* bp = bbase + kt * 8;
                    b[0][0] = __float_as_uint(bp[0]);
                    b[0][1] = __float_as_uint(bp[4]);
                    b[1][0] = __float_as_uint(bp[8 * 108]);
                    b[1][1] = __float_as_uint(bp[8 * 108 + 4]);
                    mma_tf32(c[0], a, b[0]);
                    mma_tf32(c[1], a, b[1]);
                }

#pragma unroll
                for (int nf = 0; nf < 2; nf++) {
                    int n0 = ng * 16 + nf * 8 + 2 * qi;
                    float bias0 = sBias[n0];
                    float bias1 = sBias[n0 + 1];
                    rowsum[pass * 2]     += __expf(c[nf][0] + bias0) + __expf(c[nf][1] + bias1);
                    rowsum[pass * 2 + 1] += __expf(c[nf][2] + bias0) + __expf(c[nf][3] + bias1);
                }
            }
            __syncthreads();
            cur ^= 1;
        }
    }

    // cross-lane reduce and publish
#pragma unroll
    for (int j = 0; j < 4; j++) {
        rowsum[j] += __shfl_xor_sync(0xffffffffu, rowsum[j], 1);
        rowsum[j] += __shfl_xor_sync(0xffffffffu, rowsum[j], 2);
    }
    if (tid < 512 && qi == 0) {
#pragma unroll
        for (int j = 0; j < 4; j++) {
            int row = (j >> 1) * 32 + mg * 16 + (j & 1) * 8 + grp;
            sSum[row * 8 + ng] = rowsum[j];
        }
    }
    __syncthreads();
    if (tid < 64) {
        float s = 0.0f;
#pragma unroll
        for (int w = 0; w < 8; w++) s += sSum[tid * 8 + w];
        if (tid < T) atomicAdd(&g_sumexp[tid], s);
    }
    __threadfence();
    __syncthreads();
    if (tid == 0) atomicAdd(&g_cnt1, 1);
}

// ---------------- launch ----------------
extern "C" void kernel_launch(void* const* d_in, const int* in_sizes, int n_in,
                              void* d_out, int out_size) {
    const int*   context  = (const int*)d_in[0];
    const int*   desc     = (const int*)d_in[2];
    const float* emb_ctx  = (const float*)d_in[3];
    const float* emb_dec  = (const float*)d_in[4];
    const float* w1       = (const float*)d_in[5];
    const float* b1       = (const float*)d_in[6];
    const float* w_ih     = (const float*)d_in[7];
    const float* w_hh     = (const float*)d_in[8];
    const float* b_ih     = (const float*)d_in[9];
    const float* b_hh     = (const float*)d_in[10];
    const float* w_out    = (const float*)d_in[11];
    const float* b_out    = (const float*)d_in[12];
    float* out = (float*)d_out;

    const int main_smem = MAIN_SMEM_FLOATS * (int)sizeof(float);   // 141312 B
    cudaFuncSetAttribute(k_main, cudaFuncAttributeMaxDynamicSharedMemorySize, main_smem);

    k_pre<<<120, 320>>>(context, emb_ctx, desc, emb_dec, w_ih, b_ih);
    k_main<<<148, 600, main_smem>>>(w_hh, b_hh, w_out, b_out, w1, b1, desc, out);
}

// round 12
// speedup vs baseline: 1.7522x; 1.0343x over previous
#include <cuda_runtime.h>
#include <math.h>

#define VOCAB 100000
#define EMB   100
#define HID   100
#define CTX   60
#define FACT  20
#define T     60
#define NTILES 782        // ceil(100000 / 128)
#define NWORK  147        // logits worker blocks

typedef unsigned long long u64;
typedef unsigned int u32;

// ---------------- scratch ----------------
__device__ float g_facts[CTX * EMB];
__device__ float g_h0[HID];
__device__ float g_gi[T * 3 * HID];
__device__ float g_H[T * HID];
__device__ float g_sumexp[T];
__device__ int   g_flag;
__device__ int   g_cnt0;      // h0 rows done
__device__ int   g_cnt1;      // worker blocks done
__device__ float g_sink;

__device__ __forceinline__ float sigmoidf_(float x) {
    return 1.0f / (1.0f + __expf(-x));
}
__device__ __forceinline__ void ffma2(u64 &d, u64 a, u64 b) {
    asm("fma.rn.f32x2 %0, %1, %2, %0;" : "+l"(d) : "l"(a), "l"(b));
}
__device__ __forceinline__ float f2_lo(u64 v) { return __int_as_float((int)(v & 0xffffffffull)); }
__device__ __forceinline__ float f2_hi(u64 v) { return __int_as_float((int)(v >> 32)); }
__device__ __forceinline__ unsigned to_tf32(float f) {
    unsigned r;
    asm("cvt.rna.tf32.f32 %0, %1;" : "=r"(r) : "f"(f));
    return r;
}
__device__ __forceinline__ void mma_tf32(float* c, const unsigned* a, const unsigned* b) {
    asm volatile(
        "mma.sync.aligned.m16n8k8.row.col.f32.tf32.tf32.f32 "
        "{%0,%1,%2,%3}, {%4,%5,%6,%7}, {%8,%9}, {%0,%1,%2,%3};"
        : "+f"(c[0]), "+f"(c[1]), "+f"(c[2]), "+f"(c[3])
        : "r"(a[0]), "r"(a[1]), "r"(a[2]), "r"(a[3]), "r"(b[0]), "r"(b[1]));
}
__device__ __forceinline__ u32 s2u(const void* p) {
    return (u32)__cvta_generic_to_shared(p);
}
__device__ __forceinline__ void ldsm_x4(unsigned* r, u32 addr) {
    asm volatile("ldmatrix.sync.aligned.m8n8.x4.shared.b16 {%0,%1,%2,%3}, [%4];"
                 : "=r"(r[0]), "=r"(r[1]), "=r"(r[2]), "=r"(r[3]) : "r"(addr));
}
__device__ __forceinline__ void mbar_init(u32 addr, u32 cnt) {
    asm volatile("mbarrier.init.shared.b64 [%0], %1;" :: "r"(addr), "r"(cnt) : "memory");
}
__device__ __forceinline__ void mbar_expect(u32 addr, u32 bytes) {
    asm volatile("mbarrier.arrive.expect_tx.shared.b64 _, [%0], %1;"
                 :: "r"(addr), "r"(bytes) : "memory");
}
__device__ __forceinline__ void bulk_g2s(u32 dst, const void* src, u32 bytes, u32 mbar) {
    asm volatile("cp.async.bulk.shared::cta.global.mbarrier::complete_tx::bytes [%0], [%1], %2, [%3];"
                 :: "r"(dst), "l"(src), "r"(bytes), "r"(mbar) : "memory");
}
__device__ __forceinline__ void mbar_wait(u32 addr, u32 parity) {
    asm volatile(
        "{\n\t"
        ".reg .pred P;\n\t"
        "WAIT_%=:\n\t"
        "mbarrier.try_wait.parity.acquire.cta.shared::cta.b64 P, [%0], %1, 0x989680;\n\t"
        "@P bra.uni DONE_%=;\n\t"
        "bra.uni WAIT_%=;\n\t"
        "DONE_%=:\n\t"
        "}"
        :: "r"(addr), "r"(parity) : "memory");
}
__device__ __forceinline__ void fence_proxy_async_cta() {
    asm volatile("fence.proxy.async.shared::cta;" ::: "memory");
}

// ---------------- K_pre: gi (blocks 0..59) + facts (blocks 60..119) + resets ----------------
__global__ void __launch_bounds__(320) k_pre(const int* __restrict__ ctx,
                                             const float* __restrict__ emb_ctx,
                                             const int* __restrict__ desc,
                                             const float* __restrict__ emb_dec,
                                             const float* __restrict__ w_ih,
                                             const float* __restrict__ b_ih) {
    int bid = blockIdx.x;
    int j = threadIdx.x;
    if (bid < 60) {
        int t = bid;
        __shared__ __align__(16) float x[EMB];
        __shared__ int tok;
        if (j == 0) tok = (t == 0) ? 1 : desc[t - 1];
        __syncthreads();
        if (j < EMB) x[j] = emb_dec[(long)tok * EMB + j];
        __syncthreads();
        if (j < 3 * HID) {
            const float4* w4 = (const float4*)(w_ih + (long)j * EMB);
            const float4* x4 = (const float4*)x;
            float a0 = b_ih[j], a1 = 0.0f, a2 = 0.0f, a3 = 0.0f;
#pragma unroll
            for (int k = 0; k < 25; k++) {
                float4 w = w4[k];
                float4 h = x4[k];
                a0 += w.x * h.x; a1 += w.y * h.y; a2 += w.z * h.z; a3 += w.w * h.w;
            }
            g_gi[t * (3 * HID) + j] = (a0 + a1) + (a2 + a3);
        }
    } else {
        int f = bid - 60;
        if (f == 0 && j < T) g_sumexp[j] = 0.0f;
        if (f == 0 && j == 0) { g_flag = 0; g_cnt0 = 0; g_cnt1 = 0; }
        __shared__ int toks[FACT];
        if (j < FACT) toks[j] = ctx[f * FACT + j];
        __syncthreads();
        if (j < EMB) {
            float ee = (float)j * (1.0f / 99.0f);
            float acc = 0.0f;
#pragma unroll
            for (int p = 0; p < FACT; p++) {
                float s = (float)p * (1.0f / 19.0f);
                float l = 1.0f - s - ee * (1.0f - 2.0f * s);
                acc += emb_ctx[(long)toks[p] * EMB + j] * l;
            }
            g_facts[f * EMB + j] = acc;
        }
    }
}

// ---------------- K_main smem layout (floats) ----------------
// workers: sA 64*108 | sB0 128*100+4 | sB1 128*100+4 | bias0 128 | bias1 128 | sSum 64*8 | mbar 2*u64
#define SA_F    (64 * 108)                  // 6912
#define SBN_F   (128 * 100 + 4)             // 12804
#define OFF_SB0 (SA_F)
#define OFF_SB1 (OFF_SB0 + SBN_F)
#define OFF_BI0 (OFF_SB1 + SBN_F)
#define OFF_BI1 (OFF_BI0 + 128)
#define OFF_SUM (OFF_BI1 + 128)
#define OFF_MBAR (OFF_SUM + 64 * 8)         // 33288 floats -> byte 133152 (8-aligned)
#define MAIN_SMEM_FLOATS (OFF_MBAR + 4)

__global__ void __launch_bounds__(600, 1) k_main(const float* __restrict__ w_hh,
                                                 const float* __restrict__ b_hh,
                                                 const float* __restrict__ w_out,
                                                 const float* __restrict__ b_out,
                                                 const float* __restrict__ w1,
                                                 const float* __restrict__ b1,
                                                 const int* __restrict__ desc,
                                                 float* __restrict__ out) {
    extern __shared__ __align__(16) float dyn[];
    int tid = threadIdx.x;

    if (blockIdx.x == 0) {
        // ================= GRU recurrence + token logits + final loss =================
        float* sgi = dyn;            // 18000
        float* h   = dyn + 18000;    // 100 (byte 72000, 16-aligned)
        float* ps  = h + 100;        // 600
        float* tl  = ps + 600;       // 64
        float* red = tl + 64;        // 2

        int outj = tid % 300;
        int half = tid / 300;
        int kbeg = half ? 52 : 0;          // byte offsets 0 / 208: both 16B-aligned
        // nd2: half0 -> 13 double2 (floats 0..51), half1 -> 12 (floats 52..99)

        u64 w2[26];
        {
            const double2* wr = (const double2*)(w_hh + (long)outj * HID + kbeg);
#pragma unroll
            for (int k = 0; k < 13; k++) {
                if (k + half < 13) {
                    double2 d = wr[k];
                    w2[2 * k]     = (u64)__double_as_longlong(d.x);
                    w2[2 * k + 1] = (u64)__double_as_longlong(d.y);
                }
            }
        }
        float bhr = 0.0f, bhz = 0.0f, bhn = 0.0f;
        if (tid < HID) {
            bhr = b_hh[tid];
            bhz = b_hh[HID + tid];
            bhn = b_hh[2 * HID + tid];
        }

        for (int i = tid; i < T * 3 * HID; i += 600) sgi[i] = g_gi[i];

        // wait for workers to publish h0 (100 rows)
        if (tid == 0) {
            while (*(volatile int*)&g_cnt0 < 100) __nanosleep(32);
        }
        __syncthreads();
        __threadfence();
        if (tid < HID) h[tid] = *((volatile float*)&g_h0[tid]);
        __syncthreads();

        const double2* h2 = (const double2*)(h + kbeg);
        for (int t = 0; t < T; t++) {
            {
                u64 a0 = 0ull, a1 = 0ull;
#pragma unroll
                for (int k = 0; k < 13; k++) {
                    if (k + half < 13) {
                        double2 d = h2[k];
                        ffma2(a0, w2[2 * k],     (u64)__double_as_longlong(d.x));
                        ffma2(a1, w2[2 * k + 1], (u64)__double_as_longlong(d.y));
                    }
                }
                ps[tid] = (f2_lo(a0) + f2_hi(a0)) + (f2_lo(a1) + f2_hi(a1));
            }
            __syncthreads();

            if (tid < HID) {
                float ghr = ps[tid]       + ps[tid + 300] + bhr;
                float ghz = ps[tid + 100] + ps[tid + 400] + bhz;
                float ghn = ps[tid + 200] + ps[tid + 500] + bhn;
                const float* gi = sgi + t * 300;
                float r = sigmoidf_(gi[tid] + ghr);
                float z = sigmoidf_(gi[HID + tid] + ghz);
                float a = gi[2 * HID + tid] + r * ghn;
                float ex = __expf(2.0f * a);
                float n = 1.0f - __fdividef(2.0f, ex + 1.0f);
                float hn = (1.0f - z) * n + z * h[tid];
                h[tid] = hn;
                g_H[t * HID + tid] = hn;
            }
            __syncthreads();
        }
        __threadfence();
        __syncthreads();
        if (tid == 0) *(volatile int*)&g_flag = 1;

        // ---- token logits (overlaps workers' GEMM; w_out rows are L2-warm) ----
        {
            int wid = tid >> 5;
            int lane = tid & 31;
            if (wid < 15) {
#pragma unroll
                for (int i = 0; i < 4; i++) {
                    int t = wid * 4 + i;
                    int tok = desc[t];
                    const float* wr = w_out + (size_t)tok * HID;
                    const float* hr = g_H + t * HID;
                    float acc = wr[lane] * hr[lane]
                              + wr[lane + 32] * hr[lane + 32]
                              + wr[lane + 64] * hr[lane + 64];
                    if (lane < 4) acc += wr[lane + 96] * hr[lane + 96];
#pragma unroll
                    for (int off = 16; off; off >>= 1)
                        acc += __shfl_down_sync(0xffffffffu, acc, off);
                    if (lane == 0) tl[t] = acc + b_out[tok];
                }
            }
        }

        // ---- wait for all workers, then final loss ----
        if (tid == 0) {
            while (*(volatile int*)&g_cnt1 < NWORK) __nanosleep(64);
        }
        __syncthreads();
        __threadfence();
        {
            float v = 0.0f;
            if (tid < T) v = logf(((volatile float*)g_sumexp)[tid]) - tl[tid];
            if (tid < 64) {
#pragma unroll
                for (int off = 16; off; off >>= 1)
                    v += __shfl_down_sync(0xffffffffu, v, off);
                if ((tid & 31) == 0) red[tid >> 5] = v;
            }
            __syncthreads();
            if (tid == 0) out[0] = red[0] + red[1];
        }
        return;
    }

    // ================= workers: h0, pre-stage + L2 warm, single M=64 GEMM pass =================
    float* sA = dyn;
    float* sBb[2] = { dyn + OFF_SB0, dyn + OFF_SB1 };
    float* sBi[2] = { dyn + OFF_BI0, dyn + OFF_BI1 };
    float* sSum = dyn + OFF_SUM;
    u32 mb[2];
    mb[0] = s2u(dyn + OFF_MBAR);
    mb[1] = mb[0] + 8;

    int bix = blockIdx.x - 1;   // 0..146
    int lane = tid & 31;
    int warp = tid >> 5;
    int nmine = (NTILES - 1 - bix) / NWORK + 1;   // 5 or 6

    // zero both B buffers (pad word + boundary-tile hygiene: everything finite)
    for (int i = tid; i < 2 * SBN_F; i += 600) sBb[0][i] = 0.0f;

    // ---- h0 row (blocks 1..100) ----
    if (bix < 100) {
        float acc = 0.0f;
        if (tid < 512) {
            const float* wr = w1 + (long)bix * (CTX * HID);
            for (int k = tid; k < CTX * HID; k += 512)
                acc += g_facts[k] * wr[k];
#pragma unroll
            for (int off = 16; off; off >>= 1)
                acc += __shfl_down_sync(0xffffffffu, acc, off);
            if (lane == 0) sSum[warp] = acc;
        }
        __syncthreads();
        if (tid == 0) {
            float tot = 0.0f;
#pragma unroll
            for (int w = 0; w < 16; w++) tot += sSum[w];
            g_h0[bix] = tot + b1[bix];
            __threadfence();
            atomicAdd(&g_cnt0, 1);
        }
        __syncthreads();
    } else {
        __syncthreads();   // keep barrier counts uniform vs h0 branch
        __syncthreads();
    }

    // ---- mbarrier init + pre-stage tiles 0,1 (B doesn't depend on H) ----
    if (tid == 0) {
        mbar_init(mb[0], 1);
        mbar_init(mb[1], 1);
        fence_proxy_async_cta();
    }
    __syncthreads();

    auto stageB = [&](int li) {   // tid 0 only
        int tile = bix + li * NWORK;
        if (tile >= NTILES) return;
        int buf = li & 1;
        int N0 = tile * 128;
        int rows = VOCAB - N0; if (rows > 128) rows = 128;
        u32 wb = (u32)rows * 400u;
        u32 bb = (u32)rows * 4u;
        mbar_expect(mb[buf], wb + bb);
        bulk_g2s(s2u(sBb[buf]), w_out + (size_t)N0 * HID, wb, mb[buf]);
        bulk_g2s(s2u(sBi[buf]), b_out + N0, bb, mb[buf]);
    };

    if (tid == 0) { stageB(0); stageB(1); }

    // ---- warm L2 with the REMAINING tiles while the recurrence runs ----
    {
        float acc = 0.0f;
        const float4* w4 = (const float4*)w_out;
        for (int li = 2; li < nmine; li++) {
            int N0 = (bix + li * NWORK) * 128;
            for (int i = tid; i < 128 * 25; i += 600) {
                int n = i / 25;
                if (N0 + n < VOCAB) {
                    float4 v = __ldg(&w4[(size_t)(N0 + n) * 25 + (i - n * 25)]);
                    acc += v.x + v.y + v.z + v.w;
                }
            }
        }
        if (acc == 1.23456789e30f) g_sink = acc;   // never true; defeats DCE
    }

    // ---- wait for full H, stage A once (tf32, zero-padded 64x108) ----
    if (tid == 0) {
        while (*(volatile int*)&g_flag < 1) __nanosleep(64);
    }
    __syncthreads();
    __threadfence();
    for (int i = tid; i < SA_F; i += 600) {
        int m = i / 108, k = i - m * 108;
        float v = (m < T && k < HID) ? g_H[m * HID + k] : 0.0f;
        sA[i] = __uint_as_float(to_tf32(v));
    }
    __syncthreads();

    int mg = warp >> 3;        // 0..1 (m32 group)
    int ng = warp & 7;         // 0..7 (n16 group)
    int grp = lane >> 2;       // 0..7
    int qi = lane & 3;         // 0..3

    u32 a_addr[2];
#pragma unroll
    for (int mi = 0; mi < 2; mi++)
        a_addr[mi] = s2u(sA + (mg * 32 + mi * 16 + (lane & 15)) * 108 + 4 * (lane >> 4));

    float rowsum[4] = {0.f, 0.f, 0.f, 0.f};

#pragma unroll 1
    for (int li = 0; li < nmine; li++) {
        if (tid == 0 && li >= 1) stageB(li + 1);
        mbar_wait(mb[li & 1], (u32)((li >> 1) & 1));

        int tile = bix + li * NWORK;
        int N0 = tile * 128;
        if (N0 + 128 > VOCAB) {                 // boundary tile only
            if (tid < 128 && N0 + tid >= VOCAB) sBi[li & 1][tid] = -1e30f;
            __syncthreads();
        }

        if (tid < 512) {
            const float* sB = sBb[li & 1];
            const float* sBias = sBi[li & 1];

            float c[2][2][4];
#pragma unroll
            for (int mi = 0; mi < 2; mi++)
#pragma unroll
                for (int nf = 0; nf < 2; nf++)
#pragma unroll
                    for (int r = 0; r < 4; r++) c[mi][nf][r] = 0.0f;

            const float* bbase = sB + (ng * 16 + grp) * 100 + qi;
#pragma unroll
            for (int kt = 0; kt < 13; kt++) {
                unsigned a[2][4];
                ldsm_x4(a[0], a_addr[0] + kt * 32);
                ldsm_x4(a[1], a_addr[1] + kt * 32);
                unsigned b[2][2];
                const float* bp = bbase + kt * 8;
                b[0][0] = __float_as_uint(bp[0]);
                b[0][1] = __float_as_uint(bp[4]);
                b[1][0] = __float_as_uint(bp[800]);        // +8 rows
                b[1][1] = __float_as_uint(bp[804]);
#pragma unroll
                for (int mi = 0; mi < 2; mi++) {
                    mma_tf32(c[mi][0], a[mi], b[0]);
                    mma_tf32(c[mi][1], a[mi], b[1]);
                }
            }

#pragma unroll
            for (int nf = 0; nf < 2; nf++) {
                int n0 = ng * 16 + nf * 8 + 2 * qi;
                float bias0 = sBias[n0];
                float bias1 = sBias[n0 + 1];
#pragma unroll
                for (int mi = 0; mi < 2; mi++) {
                    rowsum[mi * 2]     += __expf(c[mi][nf][0] + bias0) + __expf(c[mi][nf][1] + bias1);
                    rowsum[mi * 2 + 1] += __expf(c[mi][nf][2] + bias0) + __expf(c[mi][nf][3] + bias1);
                }
            }
        }
        __syncthreads();        // all readers done before buffer is restaged
    }

    // cross-lane reduce over qi and publish
#pragma unroll
    for (int j = 0; j < 4; j++) {
        rowsum[j] += __shfl_xor_sync(0xffffffffu, rowsum[j], 1);
        rowsum[j] += __shfl_xor_sync(0xffffffffu, rowsum[j], 2);
    }
    if (tid < 512 && qi == 0) {
#pragma unroll
        for (int j = 0; j < 4; j++) {
            int row = mg * 32 + (j >> 1) * 16 + (j & 1) * 8 + grp;
            sSum[row * 8 + ng] = rowsum[j];
        }
    }
    __syncthreads();
    if (tid < 64) {
        float s = 0.0f;
#pragma unroll
        for (int w = 0; w < 8; w++) s += sSum[tid * 8 + w];
        if (tid < T) atomicAdd(&g_sumexp[tid], s);
    }
    __threadfence();
    __syncthreads();
    if (tid == 0) atomicAdd(&g_cnt1, 1);
}

// ---------------- launch ----------------
extern "C" void kernel_launch(void* const* d_in, const int* in_sizes, int n_in,
                              void* d_out, int out_size) {
    const int*   context  = (const int*)d_in[0];
    const int*   desc     = (const int*)d_in[2];
    const float* emb_ctx  = (const float*)d_in[3];
    const float* emb_dec  = (const float*)d_in[4];
    const float* w1       = (const float*)d_in[5];
    const float* b1       = (const float*)d_in[6];
    const float* w_ih     = (const float*)d_in[7];
    const float* w_hh     = (const float*)d_in[8];
    const float* b_ih     = (const float*)d_in[9];
    const float* b_hh     = (const float*)d_in[10];
    const float* w_out    = (const float*)d_in[11];
    const float* b_out    = (const float*)d_in[12];
    float* out = (float*)d_out;

    const int main_smem = MAIN_SMEM_FLOATS * (int)sizeof(float);   // 133168 B
    cudaFuncSetAttribute(k_main, cudaFuncAttributeMaxDynamicSharedMemorySize, main_smem);

    k_pre<<<120, 320>>>(context, emb_ctx, desc, emb_dec, w_ih, b_ih);
    k_main<<<148, 600, main_smem>>>(w_hh, b_hh, w_out, b_out, w1, b1, desc, out);
}